// round 1
// baseline (speedup 1.0000x reference)
#include <cuda_runtime.h>

// Problem constants
#define BW    2048
#define NTOK  49
#define CDIM  384
#define HEADS 12
#define HD    32
#define NWIN  64

// Scratch (device globals: allocation-free)
__device__ float g_Q[BW * HEADS * NTOK * HD];
__device__ float g_K[BW * HEADS * NTOK * HD];
__device__ float g_V[BW * HEADS * NTOK * HD];
__device__ float g_AO[BW * NTOK * CDIM];

__device__ __forceinline__ unsigned f2tf(float x) {
    unsigned u;
    asm("cvt.rna.tf32.f32 %0, %1;" : "=r"(u) : "f"(x));
    return u;
}

__device__ __forceinline__ void mma8(float* c, const unsigned* a, const unsigned* b) {
    asm volatile(
        "mma.sync.aligned.m16n8k8.row.col.f32.tf32.tf32.f32 "
        "{%0,%1,%2,%3}, {%4,%5,%6,%7}, {%8,%9}, {%0,%1,%2,%3};"
        : "+f"(c[0]), "+f"(c[1]), "+f"(c[2]), "+f"(c[3])
        : "r"(a[0]), "r"(a[1]), "r"(a[2]), "r"(a[3]), "r"(b[0]), "r"(b[1]));
}

// ---------------------------------------------------------------------------
// TF32 GEMM: C[M x N] = A[M x 384] * W[384 x N] + bias
// BM=128, BN=128, BK=16, 256 threads, warp tile 64x32, double-buffered smem.
// EPI==0: QKV epilogue (scatter to g_Q (scaled), g_K, g_V)
// EPI==1: plain epilogue to out (proj), A source = g_AO
// ---------------------------------------------------------------------------
template <int N, int EPI>
__global__ void __launch_bounds__(256) gemm_tf32(
    const float* __restrict__ Ain, const float* __restrict__ W,
    const float* __restrict__ bias, float* __restrict__ out)
{
    __shared__ float sA[2][16 * 132];   // [k][m], padded stride 132
    __shared__ float sB[2][16 * 132];   // [k][n], padded stride 132

    const float* A = (EPI == 0) ? Ain : (const float*)g_AO;

    const int tid = threadIdx.x;
    const int lane = tid & 31;
    const int warp = tid >> 5;
    const int wm = warp >> 2;   // 0..1 -> m offset wm*64
    const int wn = warp & 3;    // 0..3 -> n offset wn*32
    const int rowBase = blockIdx.x * 128;
    const int colBase = blockIdx.y * 128;

    float acc[4][4][4];
#pragma unroll
    for (int mi = 0; mi < 4; mi++)
#pragma unroll
        for (int ni = 0; ni < 4; ni++)
#pragma unroll
            for (int k = 0; k < 4; k++) acc[mi][ni][k] = 0.f;

    float4 ra[2], rb[2];

    // load-index decode (constant per thread)
    const int ar0 = tid >> 2,        ak0 = (tid & 3) << 2;
    const int ar1 = (tid + 256) >> 2, ak1 = ((tid + 256) & 3) << 2;
    const int bk0 = tid >> 5,        bn0 = (tid & 31) << 2;
    const int bk1 = (tid + 256) >> 5, bn1 = ((tid + 256) & 31) << 2;

#define LOADG(kt)                                                                  \
    do {                                                                           \
        ra[0] = *(const float4*)(A + (rowBase + ar0) * 384 + (kt) * 16 + ak0);     \
        ra[1] = *(const float4*)(A + (rowBase + ar1) * 384 + (kt) * 16 + ak1);     \
        rb[0] = *(const float4*)(W + ((kt) * 16 + bk0) * N + colBase + bn0);       \
        rb[1] = *(const float4*)(W + ((kt) * 16 + bk1) * N + colBase + bn1);       \
    } while (0)

#define STORES(buf)                                                                \
    do {                                                                           \
        float* pa = &sA[buf][0];                                                   \
        pa[(ak0 + 0) * 132 + ar0] = __uint_as_float(f2tf(ra[0].x));                \
        pa[(ak0 + 1) * 132 + ar0] = __uint_as_float(f2tf(ra[0].y));                \
        pa[(ak0 + 2) * 132 + ar0] = __uint_as_float(f2tf(ra[0].z));                \
        pa[(ak0 + 3) * 132 + ar0] = __uint_as_float(f2tf(ra[0].w));                \
        pa[(ak1 + 0) * 132 + ar1] = __uint_as_float(f2tf(ra[1].x));                \
        pa[(ak1 + 1) * 132 + ar1] = __uint_as_float(f2tf(ra[1].y));                \
        pa[(ak1 + 2) * 132 + ar1] = __uint_as_float(f2tf(ra[1].z));                \
        pa[(ak1 + 3) * 132 + ar1] = __uint_as_float(f2tf(ra[1].w));                \
        float4 t0, t1;                                                             \
        t0.x = __uint_as_float(f2tf(rb[0].x));                                     \
        t0.y = __uint_as_float(f2tf(rb[0].y));                                     \
        t0.z = __uint_as_float(f2tf(rb[0].z));                                     \
        t0.w = __uint_as_float(f2tf(rb[0].w));                                     \
        t1.x = __uint_as_float(f2tf(rb[1].x));                                     \
        t1.y = __uint_as_float(f2tf(rb[1].y));                                     \
        t1.z = __uint_as_float(f2tf(rb[1].z));                                     \
        t1.w = __uint_as_float(f2tf(rb[1].w));                                     \
        *(float4*)(&sB[buf][bk0 * 132 + bn0]) = t0;                                \
        *(float4*)(&sB[buf][bk1 * 132 + bn1]) = t1;                                \
    } while (0)

    LOADG(0);
    STORES(0);
    __syncthreads();

    int cur = 0;
    const int r = lane >> 2, cthr = lane & 3;

    for (int kt = 0; kt < 24; kt++) {
        if (kt < 23) LOADG(kt + 1);

        {
            const unsigned* uA = (const unsigned*)&sA[cur][0];
            const unsigned* uB = (const unsigned*)&sB[cur][0];
#pragma unroll
            for (int ks = 0; ks < 2; ks++) {
                const int kb = ks * 8;
                unsigned af[4][4], bf[4][2];
#pragma unroll
                for (int mi = 0; mi < 4; mi++) {
                    const int m0 = wm * 64 + mi * 16 + r;
                    af[mi][0] = uA[(kb + cthr) * 132 + m0];
                    af[mi][1] = uA[(kb + cthr) * 132 + m0 + 8];
                    af[mi][2] = uA[(kb + cthr + 4) * 132 + m0];
                    af[mi][3] = uA[(kb + cthr + 4) * 132 + m0 + 8];
                }
#pragma unroll
                for (int ni = 0; ni < 4; ni++) {
                    const int n0 = wn * 32 + ni * 8 + r;
                    bf[ni][0] = uB[(kb + cthr) * 132 + n0];
                    bf[ni][1] = uB[(kb + cthr + 4) * 132 + n0];
                }
#pragma unroll
                for (int mi = 0; mi < 4; mi++)
#pragma unroll
                    for (int ni = 0; ni < 4; ni++) mma8(acc[mi][ni], af[mi], bf[ni]);
            }
        }

        if (kt < 23) STORES(cur ^ 1);
        __syncthreads();
        cur ^= 1;
    }

    // Epilogue
#pragma unroll
    for (int mi = 0; mi < 4; mi++) {
#pragma unroll
        for (int ni = 0; ni < 4; ni++) {
            const int row0 = rowBase + wm * 64 + mi * 16 + (lane >> 2);
            const int col0 = colBase + wn * 32 + ni * 8 + ((lane & 3) << 1);
#pragma unroll
            for (int k = 0; k < 4; k++) {
                const int row = row0 + (k >> 1) * 8;
                const int col = col0 + (k & 1);
                float v = acc[mi][ni][k] + bias[col];
                if (EPI == 0) {
                    const int which = col >= 768 ? 2 : (col >= 384 ? 1 : 0);
                    const int cc = col - which * 384;
                    const int bb = row / 49;
                    const int n = row - bb * 49;
                    const int dst = ((bb * 12 + (cc >> 5)) * 49 + n) * 32 + (cc & 31);
                    if (which == 0)
                        g_Q[dst] = v * 0.17677669529663689f;  // hd^-0.5
                    else if (which == 1)
                        g_K[dst] = v;
                    else
                        g_V[dst] = v;
                } else {
                    out[row * 384 + col] = v;
                }
            }
        }
    }
#undef LOADG
#undef STORES
}

// ---------------------------------------------------------------------------
// Attention kernel: one CTA (128 threads) per (window b, head h)
// scores = Qs Kᵀ + bias[rel_idx] + mask[b%64]; softmax; out = P V -> g_AO
// ---------------------------------------------------------------------------
__global__ void __launch_bounds__(128) attn_kernel(
    const float* __restrict__ mask, const float* __restrict__ bias_table,
    const int* __restrict__ rel_idx)
{
    __shared__ float sq[49][33];   // q row-major (Q already scaled)
    __shared__ float skT[32][56];  // K transposed: skT[d][m]
    __shared__ float sv[49][33];   // v row-major
    __shared__ float ss[49][56];   // scores / probs

    const int b = blockIdx.x;
    const int h = blockIdx.y;
    const int tid = threadIdx.x;
    const int lane = tid & 31;
    const int warp = tid >> 5;

    const float* Qb = g_Q + ((b * 12 + h) * 49) * 32;
    const float* Kb = g_K + ((b * 12 + h) * 49) * 32;
    const float* Vb = g_V + ((b * 12 + h) * 49) * 32;

    // Load tiles (49x32 each), K transposed
    for (int f = tid; f < 392; f += 128) {
        const int row = f >> 3;
        const int c4 = (f & 7) << 2;
        float4 a = *(const float4*)(Qb + row * 32 + c4);
        sq[row][c4] = a.x; sq[row][c4 + 1] = a.y; sq[row][c4 + 2] = a.z; sq[row][c4 + 3] = a.w;
        float4 kk = *(const float4*)(Kb + row * 32 + c4);
        skT[c4][row] = kk.x; skT[c4 + 1][row] = kk.y; skT[c4 + 2][row] = kk.z; skT[c4 + 3][row] = kk.w;
        float4 vv = *(const float4*)(Vb + row * 32 + c4);
        sv[row][c4] = vv.x; sv[row][c4 + 1] = vv.y; sv[row][c4 + 2] = vv.z; sv[row][c4 + 3] = vv.w;
    }
    __syncthreads();

    const int lane2 = lane + 32;
    const bool has2 = lane2 < 49;
    const int m2 = has2 ? lane2 : 0;
    const float* maskw = mask + (b & 63) * 2401;

    // Phase 1: scores. Warp handles rows n = warp + 4*j; 4-row register blocks.
    for (int j0 = 0; j0 < 13; j0 += 4) {
        int n[4], nc[4];
        float a0[4], a1[4];
#pragma unroll
        for (int i = 0; i < 4; i++) {
            n[i] = warp + 4 * (j0 + i);
            nc[i] = n[i] < 49 ? n[i] : 48;
            a0[i] = 0.f;
            a1[i] = 0.f;
        }
#pragma unroll
        for (int d = 0; d < 32; d++) {
            const float k0 = skT[d][lane];
            const float k1 = skT[d][m2];
#pragma unroll
            for (int i = 0; i < 4; i++) {
                const float qv = sq[nc[i]][d];
                a0[i] += qv * k0;
                a1[i] += qv * k1;
            }
        }
#pragma unroll
        for (int i = 0; i < 4; i++) {
            if (n[i] < 49) {
                const int base = n[i] * 49;
                ss[n[i]][lane] =
                    a0[i] + bias_table[rel_idx[base + lane] * 12 + h] + maskw[base + lane];
                if (has2)
                    ss[n[i]][lane2] =
                        a1[i] + bias_table[rel_idx[base + lane2] * 12 + h] + maskw[base + lane2];
            }
        }
    }
    __syncthreads();

    // Phase 2: row softmax (warp per row, shuffle reductions)
    for (int n = warp; n < 49; n += 4) {
        const float x0 = ss[n][lane];
        const float x1 = has2 ? ss[n][lane2] : -3.0e38f;
        float mx = fmaxf(x0, x1);
#pragma unroll
        for (int o = 16; o; o >>= 1) mx = fmaxf(mx, __shfl_xor_sync(0xffffffffu, mx, o));
        const float e0 = __expf(x0 - mx);
        const float e1 = has2 ? __expf(x1 - mx) : 0.f;
        float sm = e0 + e1;
#pragma unroll
        for (int o = 16; o; o >>= 1) sm += __shfl_xor_sync(0xffffffffu, sm, o);
        const float inv = 1.f / sm;
        ss[n][lane] = e0 * inv;
        if (has2) ss[n][lane2] = e1 * inv;
    }
    __syncthreads();

    // Phase 3: out = P V (lane = d column), 4-row register blocks
    float* AOb = g_AO + (b * 49) * 384 + h * 32 + lane;
    for (int j0 = 0; j0 < 13; j0 += 4) {
        int n[4], nc[4];
        float o[4];
#pragma unroll
        for (int i = 0; i < 4; i++) {
            n[i] = warp + 4 * (j0 + i);
            nc[i] = n[i] < 49 ? n[i] : 48;
            o[i] = 0.f;
        }
#pragma unroll
        for (int m = 0; m < 49; m++) {
            const float vv = sv[m][lane];
#pragma unroll
            for (int i = 0; i < 4; i++) o[i] += ss[nc[i]][m] * vv;
        }
#pragma unroll
        for (int i = 0; i < 4; i++)
            if (n[i] < 49) AOb[n[i] * 384] = o[i];
    }
}

// ---------------------------------------------------------------------------
extern "C" void kernel_launch(void* const* d_in, const int* in_sizes, int n_in,
                              void* d_out, int out_size)
{
    const float* x          = (const float*)d_in[0];
    const float* mask       = (const float*)d_in[1];
    const float* qkv_w      = (const float*)d_in[2];
    const float* qkv_b      = (const float*)d_in[3];
    const float* proj_w     = (const float*)d_in[4];
    const float* proj_b     = (const float*)d_in[5];
    const float* bias_table = (const float*)d_in[6];
    const int*   rel_idx    = (const int*)d_in[7];
    float*       out        = (float*)d_out;

    // QKV: (100352 x 384) @ (384 x 1152), scatter into g_Q/g_K/g_V
    gemm_tf32<1152, 0><<<dim3(784, 9), 256>>>(x, qkv_w, qkv_b, nullptr);

    // Windowed attention into g_AO
    attn_kernel<<<dim3(2048, 12), 128>>>(mask, bias_table, rel_idx);

    // Proj: (100352 x 384) @ (384 x 384) + bias -> out
    gemm_tf32<384, 1><<<dim3(784, 3), 256>>>(nullptr, proj_w, proj_b, out);
}

// round 3
// speedup vs baseline: 1.1055x; 1.1055x over previous
#include <cuda_runtime.h>
#include <cstdint>

#define BW    2048
#define NTOK  49
#define CDIM  384
#define HEADS 12
#define HD    32
#define NWIN  64

// ---------------------------------------------------------------------------
// Device scratch (allocation-free)
// ---------------------------------------------------------------------------
__device__ float g_Q [BW * HEADS * NTOK * HD];
__device__ float g_K [BW * HEADS * NTOK * HD];
__device__ float g_V [BW * HEADS * NTOK * HD];
__device__ float g_AO[BW * NTOK * CDIM];
__device__ float g_WT1[1152 * 384];                 // qkv_w^T, tf32-rounded  [n][k]
__device__ float g_WT2[384 * 384];                  // proj_w^T, tf32-rounded [n][k]
__device__ float g_BM [NWIN * HEADS * NTOK * NTOK]; // bias[rel_idx] + mask

__device__ __forceinline__ unsigned f2tf(float x) {
    unsigned u;
    asm("cvt.rna.tf32.f32 %0, %1;" : "=r"(u) : "f"(x));
    return u;
}

__device__ __forceinline__ void mma8(float* cc, const unsigned* a, const unsigned* b) {
    asm volatile(
        "mma.sync.aligned.m16n8k8.row.col.f32.tf32.tf32.f32 "
        "{%0,%1,%2,%3}, {%4,%5,%6,%7}, {%8,%9}, {%0,%1,%2,%3};"
        : "+f"(cc[0]), "+f"(cc[1]), "+f"(cc[2]), "+f"(cc[3])
        : "r"(a[0]), "r"(a[1]), "r"(a[2]), "r"(a[3]), "r"(b[0]), "r"(b[1]));
}

// ---------------------------------------------------------------------------
// Prep kernels (tiny)
// ---------------------------------------------------------------------------
template <int WHICH>
__global__ void __launch_bounds__(384) prep_wt(const float* __restrict__ w) {
    const int N = WHICH ? 384 : 1152;
    float* wt = WHICH ? g_WT2 : g_WT1;
    const int n = blockIdx.x;
    const int k = threadIdx.x;
    wt[n * 384 + k] = __uint_as_float(f2tf(w[k * N + n]));
}

__global__ void __launch_bounds__(256) prep_bm(const float* __restrict__ mask,
                                               const float* __restrict__ bt,
                                               const int* __restrict__ ri) {
    const int w = blockIdx.x, h = blockIdx.y;
    float* dst = g_BM + (w * HEADS + h) * (NTOK * NTOK);
    const float* mw = mask + w * (NTOK * NTOK);
    for (int i = threadIdx.x; i < NTOK * NTOK; i += 256)
        dst[i] = bt[ri[i] * HEADS + h] + mw[i];
}

// ---------------------------------------------------------------------------
// TF32 mma.sync GEMM, conflict-free swizzled smem.
// C[BM=256 x BN=128] = A[. x 384] * WT[. x 384]^T (+bias)
// 256 threads, 8 warps in 4(m) x 2(n), warp tile 64x64, BK=16, double buffer.
//
// smem layout per operand row: 16 float slots, k-permuted within 8-groups
// (slot 2c holds k=c, slot 2c+1 holds k=c+4), XOR-swizzled by ((row&3)<<2).
// Fragment (k=c, k=c+4) at rows r / r+8 => two LDS.64, bank-conflict-free.
// ---------------------------------------------------------------------------
template <int EPI>
__global__ void __launch_bounds__(256) gemm_mma(const float* __restrict__ Ain,
                                                const float* __restrict__ bias,
                                                float* __restrict__ out) {
    __shared__ float sA[2][256 * 16];   // 16KB / stage
    __shared__ float sB[2][128 * 16];   // 8KB  / stage

    const float* A  = (EPI == 0) ? Ain : (const float*)g_AO;
    const float* WT = (EPI == 0) ? (const float*)g_WT1 : (const float*)g_WT2;

    const int tid  = threadIdx.x;
    const int lane = tid & 31;
    const int warp = tid >> 5;
    const int wm   = warp >> 1;          // 0..3 -> m offset wm*64
    const int wn   = warp & 1;           // 0..1 -> n offset wn*64
    const int rowBase = blockIdx.x * 256;
    const int colBase = blockIdx.y * 128;

    float acc[4][8][4];
#pragma unroll
    for (int mi = 0; mi < 4; mi++)
#pragma unroll
        for (int ni = 0; ni < 8; ni++)
#pragma unroll
            for (int k = 0; k < 4; k++) acc[mi][ni][k] = 0.f;

    // staging decode: A atoms i=0..3 (a = tid+256i): row=a>>2 (0..255), kq=a&3
    //                 B atoms i=0..1: row 0..127
    float4 ra[4], rb[2];
    int arow[4], akq[4];
#pragma unroll
    for (int i = 0; i < 4; i++) { int a = tid + 256 * i; arow[i] = a >> 2; akq[i] = a & 3; }

    const float* Ap = A + (size_t)rowBase * 384;
    const float* Bp = WT + (size_t)colBase * 384;

#define LOADG(kt)                                                                    \
    do {                                                                             \
        _Pragma("unroll")                                                            \
        for (int i = 0; i < 4; i++)                                                  \
            ra[i] = *(const float4*)(Ap + arow[i] * 384 + (kt) * 16 + akq[i] * 4);   \
        _Pragma("unroll")                                                            \
        for (int i = 0; i < 2; i++)                                                  \
            rb[i] = *(const float4*)(Bp + arow[i] * 384 + (kt) * 16 + akq[i] * 4);   \
    } while (0)

    // slotbase(kq): 0->0, 1->1, 2->8, 3->9 ; elements j at slotbase + 2j
#define STORES(buf)                                                                  \
    do {                                                                             \
        _Pragma("unroll")                                                            \
        for (int i = 0; i < 4; i++) {                                                \
            const int sbase = ((akq[i] & 2) << 2) | (akq[i] & 1);                    \
            const int xr = (arow[i] & 3) << 2;                                       \
            float* p = &sA[buf][arow[i] * 16];                                       \
            p[(sbase + 0) ^ xr] = __uint_as_float(f2tf(ra[i].x));                    \
            p[(sbase + 2) ^ xr] = __uint_as_float(f2tf(ra[i].y));                    \
            p[(sbase + 4) ^ xr] = __uint_as_float(f2tf(ra[i].z));                    \
            p[(sbase + 6) ^ xr] = __uint_as_float(f2tf(ra[i].w));                    \
        }                                                                            \
        _Pragma("unroll")                                                            \
        for (int i = 0; i < 2; i++) {                                                \
            const int sbase = ((akq[i] & 2) << 2) | (akq[i] & 1);                    \
            const int xr = (arow[i] & 3) << 2;                                       \
            float* p = &sB[buf][arow[i] * 16];                                       \
            p[(sbase + 0) ^ xr] = rb[i].x;                                           \
            p[(sbase + 2) ^ xr] = rb[i].y;                                           \
            p[(sbase + 4) ^ xr] = rb[i].z;                                           \
            p[(sbase + 6) ^ xr] = rb[i].w;                                           \
        }                                                                            \
    } while (0)

    LOADG(0);
    STORES(0);
    __syncthreads();

    const int r = lane >> 2;
    const int c = lane & 3;
    const int xorm = (r & 3) << 1;    // XOR in 8-byte units

    int cur = 0;
    for (int kt = 0; kt < 24; kt++) {
        if (kt < 23) LOADG(kt + 1);

        const uint2* A2 = (const uint2*)sA[cur];
        const uint2* B2 = (const uint2*)sB[cur];
#pragma unroll
        for (int ks = 0; ks < 2; ks++) {
            const int uk = (ks * 4 + c) ^ xorm;
            unsigned af[4][4], bf[8][2];
#pragma unroll
            for (int mi = 0; mi < 4; mi++) {
                const int m0 = wm * 64 + mi * 16 + r;
                uint2 lo = A2[m0 * 8 + uk];
                uint2 hi = A2[(m0 + 8) * 8 + uk];
                af[mi][0] = lo.x; af[mi][1] = hi.x; af[mi][2] = lo.y; af[mi][3] = hi.y;
            }
#pragma unroll
            for (int ni = 0; ni < 8; ni++) {
                const int n0 = wn * 64 + ni * 8 + r;
                uint2 bb = B2[n0 * 8 + uk];
                bf[ni][0] = bb.x; bf[ni][1] = bb.y;
            }
#pragma unroll
            for (int mi = 0; mi < 4; mi++)
#pragma unroll
                for (int ni = 0; ni < 8; ni++) mma8(acc[mi][ni], af[mi], bf[ni]);
        }

        if (kt < 23) STORES(cur ^ 1);
        __syncthreads();
        cur ^= 1;
    }

    // -------- epilogue
#pragma unroll
    for (int mi = 0; mi < 4; mi++) {
#pragma unroll
        for (int g = 0; g < 2; g++) {
            const int row = rowBase + wm * 64 + mi * 16 + r + g * 8;
            int bb = 0, n = 0;
            if (EPI == 0) { bb = row / 49; n = row - bb * 49; }
#pragma unroll
            for (int ni = 0; ni < 8; ni++) {
                const int col = colBase + wn * 64 + ni * 8 + 2 * c;
                float2 b2 = *(const float2*)(bias + col);
                float2 v;
                v.x = acc[mi][ni][g * 2 + 0] + b2.x;
                v.y = acc[mi][ni][g * 2 + 1] + b2.y;
                if (EPI == 0) {
                    const int which = (col >= 768) ? 2 : (col >= 384 ? 1 : 0);
                    const int ccc = col - which * 384;
                    const int h = ccc >> 5, dd = ccc & 31;
                    float* dst;
                    if (which == 0) {
                        v.x *= 0.17677669529663689f;
                        v.y *= 0.17677669529663689f;
                        dst = g_Q + (((size_t)(bb * 12 + h) * 49 + n) * 32 + dd);
                    } else if (which == 1) {
                        dst = g_K + (((size_t)(bb * 12 + h) * 49 + n) * 32 + dd);
                    } else {
                        dst = g_V + (((size_t)(bb * 12 + h) * 49 + n) * 32 + dd);
                    }
                    *(float2*)dst = v;
                } else {
                    *(float2*)(out + (size_t)row * 384 + col) = v;
                }
            }
        }
    }
#undef LOADG
#undef STORES
}

// ---------------------------------------------------------------------------
// Attention: one CTA (128 threads) per (window b, head h)
// ---------------------------------------------------------------------------
template <int NR>
__device__ __forceinline__ void p1_block(int j0, int warp, int lane, int m2, bool has2,
                                         const float (*sq)[33], const float (*skT)[56],
                                         float (*ss)[56], const float* __restrict__ bm) {
    int n[NR], nc[NR];
    float a0[NR], a1[NR];
#pragma unroll
    for (int i = 0; i < NR; i++) {
        n[i] = warp + 4 * (j0 + i);
        nc[i] = n[i] < 49 ? n[i] : 48;
        a0[i] = 0.f;
        a1[i] = 0.f;
    }
#pragma unroll
    for (int d = 0; d < 32; d++) {
        const float k0 = skT[d][lane];
        const float k1 = skT[d][m2];
#pragma unroll
        for (int i = 0; i < NR; i++) {
            const float qv = sq[nc[i]][d];
            a0[i] += qv * k0;
            a1[i] += qv * k1;
        }
    }
#pragma unroll
    for (int i = 0; i < NR; i++) {
        if (n[i] < 49) {
            const int base = n[i] * 49;
            ss[n[i]][lane] = a0[i] + bm[base + lane];
            if (has2) ss[n[i]][lane + 32] = a1[i] + bm[base + lane + 32];
        }
    }
}

template <int NR>
__device__ __forceinline__ void p3_block(int j0, int warp, int lane,
                                         const float (*sv)[33], const float (*ss)[56],
                                         float* __restrict__ AOb) {
    int n[NR], nc[NR];
    float o[NR];
#pragma unroll
    for (int i = 0; i < NR; i++) {
        n[i] = warp + 4 * (j0 + i);
        nc[i] = n[i] < 49 ? n[i] : 48;
        o[i] = 0.f;
    }
#pragma unroll
    for (int m = 0; m < 49; m++) {
        const float vv = sv[m][lane];
#pragma unroll
        for (int i = 0; i < NR; i++) o[i] += ss[nc[i]][m] * vv;
    }
#pragma unroll
    for (int i = 0; i < NR; i++)
        if (n[i] < 49) AOb[n[i] * 384] = o[i];
}

__global__ void __launch_bounds__(128) attn_kernel() {
    __shared__ float sq[49][33];
    __shared__ float skT[32][56];
    __shared__ float sv[49][33];
    __shared__ float ss[49][56];

    const int b = blockIdx.x;
    const int h = blockIdx.y;
    const int tid = threadIdx.x;
    const int lane = tid & 31;
    const int warp = tid >> 5;

    const float* Qb = g_Q + ((size_t)(b * 12 + h) * 49) * 32;
    const float* Kb = g_K + ((size_t)(b * 12 + h) * 49) * 32;
    const float* Vb = g_V + ((size_t)(b * 12 + h) * 49) * 32;

    for (int f = tid; f < 392; f += 128) {
        const int row = f >> 3;
        const int c4 = (f & 7) << 2;
        float4 a = *(const float4*)(Qb + row * 32 + c4);
        sq[row][c4] = a.x; sq[row][c4 + 1] = a.y; sq[row][c4 + 2] = a.z; sq[row][c4 + 3] = a.w;
        float4 kk = *(const float4*)(Kb + row * 32 + c4);
        skT[c4][row] = kk.x; skT[c4 + 1][row] = kk.y; skT[c4 + 2][row] = kk.z; skT[c4 + 3][row] = kk.w;
        float4 vv = *(const float4*)(Vb + row * 32 + c4);
        sv[row][c4] = vv.x; sv[row][c4 + 1] = vv.y; sv[row][c4 + 2] = vv.z; sv[row][c4 + 3] = vv.w;
    }
    __syncthreads();

    const int lane2 = lane + 32;
    const bool has2 = lane2 < 49;
    const int m2 = has2 ? lane2 : 0;
    const float* bm = g_BM + ((size_t)(b & 63) * 12 + h) * 2401;

    p1_block<7>(0, warp, lane, m2, has2, sq, skT, ss, bm);
    p1_block<6>(7, warp, lane, m2, has2, sq, skT, ss, bm);
    __syncthreads();

    for (int n = warp; n < 49; n += 4) {
        const float x0 = ss[n][lane];
        const float x1 = has2 ? ss[n][lane2] : -3.0e38f;
        float mx = fmaxf(x0, x1);
#pragma unroll
        for (int o = 16; o; o >>= 1) mx = fmaxf(mx, __shfl_xor_sync(0xffffffffu, mx, o));
        const float e0 = __expf(x0 - mx);
        const float e1 = has2 ? __expf(x1 - mx) : 0.f;
        float sm = e0 + e1;
#pragma unroll
        for (int o = 16; o; o >>= 1) sm += __shfl_xor_sync(0xffffffffu, sm, o);
        const float inv = 1.f / sm;
        ss[n][lane] = e0 * inv;
        if (has2) ss[n][lane2] = e1 * inv;
    }
    __syncthreads();

    float* AOb = g_AO + (size_t)(b * 49) * 384 + h * 32 + lane;
    p3_block<7>(0, warp, lane, sv, ss, AOb);
    p3_block<6>(7, warp, lane, sv, ss, AOb);
}

// ---------------------------------------------------------------------------
extern "C" void kernel_launch(void* const* d_in, const int* in_sizes, int n_in,
                              void* d_out, int out_size) {
    const float* x          = (const float*)d_in[0];
    const float* mask       = (const float*)d_in[1];
    const float* qkv_w      = (const float*)d_in[2];
    const float* qkv_b      = (const float*)d_in[3];
    const float* proj_w     = (const float*)d_in[4];
    const float* proj_b     = (const float*)d_in[5];
    const float* bias_table = (const float*)d_in[6];
    const int*   rel_idx    = (const int*)d_in[7];
    float*       out        = (float*)d_out;

    prep_wt<0><<<1152, 384>>>(qkv_w);
    prep_wt<1><<<384, 384>>>(proj_w);
    prep_bm<<<dim3(NWIN, HEADS), 256>>>(mask, bias_table, rel_idx);

    // QKV: (100352 x 384) @ WT1^T -> scatter g_Q/g_K/g_V
    gemm_mma<0><<<dim3(392, 9), 256>>>(x, qkv_b, nullptr);

    // Windowed attention -> g_AO
    attn_kernel<<<dim3(2048, 12), 128>>>();

    // Proj: g_AO @ WT2^T + bias -> out
    gemm_mma<1><<<dim3(392, 3), 256>>>(nullptr, proj_b, out);
}

// round 4
// speedup vs baseline: 1.4719x; 1.3315x over previous
#include <cuda_runtime.h>
#include <cuda_fp16.h>
#include <cstdint>

#define BW    2048
#define NTOK  49
#define CDIM  384
#define HEADS 12
#define HD    32
#define NWIN  64

// ---------------------------------------------------------------------------
// Device scratch (allocation-free)
// ---------------------------------------------------------------------------
__device__ __half g_Xh [BW * NTOK * CDIM];          // x, fp16
__device__ __half g_AOh[BW * NTOK * CDIM];          // attention output, fp16
__device__ __half g_W1h[1152 * 384];                // qkv_w^T  [n][k] fp16
__device__ __half g_W2h[384 * 384];                 // proj_w^T [n][k] fp16
__device__ float  g_Q [BW * HEADS * NTOK * HD];
__device__ float  g_K [BW * HEADS * NTOK * HD];
__device__ float  g_V [BW * HEADS * NTOK * HD];
__device__ float  g_BM[NWIN * HEADS * NTOK * NTOK]; // bias[rel_idx] + mask

// ---------------------------------------------------------------------------
// Helpers
// ---------------------------------------------------------------------------
__device__ __forceinline__ uint32_t s2u(const void* p) {
    uint32_t a;
    asm("{ .reg .u64 t; cvta.to.shared.u64 t, %1; cvt.u32.u64 %0, t; }"
        : "=r"(a) : "l"(p));
    return a;
}

__device__ __forceinline__ void cp16(uint32_t saddr, const void* g) {
    asm volatile("cp.async.cg.shared.global [%0], [%1], 16;"
                 :: "r"(saddr), "l"(g) : "memory");
}
__device__ __forceinline__ void cp_commit() {
    asm volatile("cp.async.commit_group;" ::: "memory");
}
template <int N>
__device__ __forceinline__ void cp_wait() {
    asm volatile("cp.async.wait_group %0;" :: "n"(N) : "memory");
}

__device__ __forceinline__ void mma16(float* cc, const unsigned* a, const unsigned* b) {
    asm volatile(
        "mma.sync.aligned.m16n8k16.row.col.f32.f16.f16.f32 "
        "{%0,%1,%2,%3}, {%4,%5,%6,%7}, {%8,%9}, {%0,%1,%2,%3};"
        : "+f"(cc[0]), "+f"(cc[1]), "+f"(cc[2]), "+f"(cc[3])
        : "r"(a[0]), "r"(a[1]), "r"(a[2]), "r"(a[3]), "r"(b[0]), "r"(b[1]));
}

// ---------------------------------------------------------------------------
// Prep kernels
// ---------------------------------------------------------------------------
__global__ void __launch_bounds__(256) prep_xh(const float* __restrict__ x) {
    const int i = blockIdx.x * 256 + threadIdx.x;   // 9,633,792 float4s
    float4 v = ((const float4*)x)[i];
    __half2* dst = (__half2*)g_Xh;
    dst[2 * i]     = __floats2half2_rn(v.x, v.y);
    dst[2 * i + 1] = __floats2half2_rn(v.z, v.w);
}

template <int WHICH>
__global__ void __launch_bounds__(384) prep_wth(const float* __restrict__ w) {
    const int N = WHICH ? 384 : 1152;
    __half* wt = WHICH ? g_W2h : g_W1h;
    const int n = blockIdx.x;
    const int k = threadIdx.x;
    wt[n * 384 + k] = __float2half_rn(w[k * N + n]);
}

__global__ void __launch_bounds__(256) prep_bm(const float* __restrict__ mask,
                                               const float* __restrict__ bt,
                                               const int* __restrict__ ri) {
    const int w = blockIdx.x, h = blockIdx.y;
    float* dst = g_BM + (w * HEADS + h) * (NTOK * NTOK);
    const float* mw = mask + w * (NTOK * NTOK);
    for (int i = threadIdx.x; i < NTOK * NTOK; i += 256)
        dst[i] = bt[ri[i] * HEADS + h] + mw[i];
}

// ---------------------------------------------------------------------------
// fp16 mma.sync GEMM with cp.async 3-stage pipeline.
// C[BM=256 x BN=128] = A[. x 384] * W[. x 384]^T (+bias)
// 512 threads, 16 warps (4m x 4n), warp tile 64x32, BK=32.
// smem per stage: A [4 chunks][256 m][8 halfs] = 16KB, B [4][128][8] = 8KB.
// grid = (ncolblk, 392): x = column block so A stripes stay L2-resident.
// ---------------------------------------------------------------------------
#define STG_B  24576
#define STG_U  6144
#define NSTG   3
#define DYNSZ  (NSTG * STG_B)

template <int EPI>
__global__ void __launch_bounds__(512) gemm_h(const float* __restrict__ bias,
                                              float* __restrict__ out) {
    extern __shared__ char smem[];
    const uint32_t smem0 = s2u(smem);
    const unsigned* SU = (const unsigned*)smem;

    const __half* A  = (EPI == 0) ? g_Xh : g_AOh;
    const __half* Bw = (EPI == 0) ? (const __half*)g_W1h : (const __half*)g_W2h;

    const int tid  = threadIdx.x;
    const int lane = tid & 31;
    const int warp = tid >> 5;
    const int wm   = warp >> 2;           // 0..3 -> m = wm*64
    const int wn   = warp & 3;            // 0..3 -> n = wn*32
    const int colBase = blockIdx.x * 128;
    const int rowBase = blockIdx.y * 256;

    const __half* Ag = A + (size_t)rowBase * 384;
    const __half* Bg = Bw + (size_t)colBase * 384;

    // cp.async atom decode
    const int am0 = tid >> 2,          ac0 = tid & 3;
    const int am1 = (tid + 512) >> 2,  ac1 = (tid + 512) & 3;
    const int bn  = tid >> 2,          bc  = tid & 3;

#define LOADSTG(s, kt)                                                          \
    do {                                                                        \
        const uint32_t sb = smem0 + (s) * STG_B;                                \
        cp16(sb + ac0 * 4096 + am0 * 16, Ag + am0 * 384 + (kt) * 32 + ac0 * 8); \
        cp16(sb + ac1 * 4096 + am1 * 16, Ag + am1 * 384 + (kt) * 32 + ac1 * 8); \
        cp16(sb + 16384 + bc * 2048 + bn * 16,                                  \
             Bg + bn * 384 + (kt) * 32 + bc * 8);                               \
    } while (0)

    float acc[4][4][4];
#pragma unroll
    for (int mi = 0; mi < 4; mi++)
#pragma unroll
        for (int ni = 0; ni < 4; ni++)
#pragma unroll
            for (int k = 0; k < 4; k++) acc[mi][ni][k] = 0.f;

    LOADSTG(0, 0);
    cp_commit();
    LOADSTG(1, 1);
    cp_commit();

    const int r = lane >> 2;
    const int c = lane & 3;

    for (int kt = 0; kt < 12; kt++) {
        if (kt < 11) cp_wait<1>(); else cp_wait<0>();
        __syncthreads();
        if (kt + 2 < 12) { LOADSTG((kt + 2) % NSTG, kt + 2); cp_commit(); }

        const unsigned* SA = SU + (kt % NSTG) * STG_U;
        const unsigned* SB = SA + 4096;
#pragma unroll
        for (int ks = 0; ks < 2; ks++) {
            unsigned af[4][4], bf[4][2];
#pragma unroll
            for (int mi = 0; mi < 4; mi++) {
                const int m0 = wm * 64 + mi * 16 + r;
                af[mi][0] = SA[(2 * ks) * 1024 + m0 * 4 + c];
                af[mi][1] = SA[(2 * ks) * 1024 + (m0 + 8) * 4 + c];
                af[mi][2] = SA[(2 * ks + 1) * 1024 + m0 * 4 + c];
                af[mi][3] = SA[(2 * ks + 1) * 1024 + (m0 + 8) * 4 + c];
            }
#pragma unroll
            for (int ni = 0; ni < 4; ni++) {
                const int n0 = wn * 32 + ni * 8 + r;
                bf[ni][0] = SB[(2 * ks) * 512 + n0 * 4 + c];
                bf[ni][1] = SB[(2 * ks + 1) * 512 + n0 * 4 + c];
            }
#pragma unroll
            for (int mi = 0; mi < 4; mi++)
#pragma unroll
                for (int ni = 0; ni < 4; ni++) mma16(acc[mi][ni], af[mi], bf[ni]);
        }
        __syncthreads();
    }

    // -------- epilogue
#pragma unroll
    for (int mi = 0; mi < 4; mi++) {
#pragma unroll
        for (int g = 0; g < 2; g++) {
            const int row = rowBase + wm * 64 + mi * 16 + r + g * 8;
            int bb = 0, n = 0;
            if (EPI == 0) { bb = row / 49; n = row - bb * 49; }
#pragma unroll
            for (int ni = 0; ni < 4; ni++) {
                const int col = colBase + wn * 32 + ni * 8 + 2 * c;
                float2 b2 = *(const float2*)(bias + col);
                float2 v;
                v.x = acc[mi][ni][g * 2 + 0] + b2.x;
                v.y = acc[mi][ni][g * 2 + 1] + b2.y;
                if (EPI == 0) {
                    const int which = (col >= 768) ? 2 : (col >= 384 ? 1 : 0);
                    const int ccc = col - which * 384;
                    const int h = ccc >> 5, dd = ccc & 31;
                    float* dst;
                    if (which == 0) {
                        v.x *= 0.17677669529663689f;
                        v.y *= 0.17677669529663689f;
                        dst = g_Q + (((size_t)(bb * 12 + h) * 49 + n) * 32 + dd);
                    } else if (which == 1) {
                        dst = g_K + (((size_t)(bb * 12 + h) * 49 + n) * 32 + dd);
                    } else {
                        dst = g_V + (((size_t)(bb * 12 + h) * 49 + n) * 32 + dd);
                    }
                    *(float2*)dst = v;
                } else {
                    *(float2*)(out + (size_t)row * 384 + col) = v;
                }
            }
        }
    }
#undef LOADSTG
}

// ---------------------------------------------------------------------------
// Attention: one CTA (128 threads) per (window b, head h)
// ---------------------------------------------------------------------------
template <int NR>
__device__ __forceinline__ void p1_block(int j0, int warp, int lane, int m2, bool has2,
                                         const float (*sq)[33], const float (*skT)[56],
                                         float (*ss)[56], const float* __restrict__ bm) {
    int n[NR], nc[NR];
    float a0[NR], a1[NR];
#pragma unroll
    for (int i = 0; i < NR; i++) {
        n[i] = warp + 4 * (j0 + i);
        nc[i] = n[i] < 49 ? n[i] : 48;
        a0[i] = 0.f;
        a1[i] = 0.f;
    }
#pragma unroll
    for (int d = 0; d < 32; d++) {
        const float k0 = skT[d][lane];
        const float k1 = skT[d][m2];
#pragma unroll
        for (int i = 0; i < NR; i++) {
            const float qv = sq[nc[i]][d];
            a0[i] += qv * k0;
            a1[i] += qv * k1;
        }
    }
#pragma unroll
    for (int i = 0; i < NR; i++) {
        if (n[i] < 49) {
            const int base = n[i] * 49;
            ss[n[i]][lane] = a0[i] + bm[base + lane];
            if (has2) ss[n[i]][lane + 32] = a1[i] + bm[base + lane + 32];
        }
    }
}

template <int NR>
__device__ __forceinline__ void p3_block(int j0, int warp, int lane,
                                         const float (*sv)[33], const float (*ss)[56],
                                         __half* __restrict__ AOb) {
    int n[NR], nc[NR];
    float o[NR];
#pragma unroll
    for (int i = 0; i < NR; i++) {
        n[i] = warp + 4 * (j0 + i);
        nc[i] = n[i] < 49 ? n[i] : 48;
        o[i] = 0.f;
    }
#pragma unroll
    for (int m = 0; m < 49; m++) {
        const float vv = sv[m][lane];
#pragma unroll
        for (int i = 0; i < NR; i++) o[i] += ss[nc[i]][m] * vv;
    }
#pragma unroll
    for (int i = 0; i < NR; i++)
        if (n[i] < 49) AOb[n[i] * 384] = __float2half_rn(o[i]);
}

__global__ void __launch_bounds__(128) attn_kernel() {
    __shared__ float sq[49][33];
    __shared__ float skT[32][56];
    __shared__ float sv[49][33];
    __shared__ float ss[49][56];

    const int b = blockIdx.x;
    const int h = blockIdx.y;
    const int tid = threadIdx.x;
    const int lane = tid & 31;
    const int warp = tid >> 5;

    const float* Qb = g_Q + ((size_t)(b * 12 + h) * 49) * 32;
    const float* Kb = g_K + ((size_t)(b * 12 + h) * 49) * 32;
    const float* Vb = g_V + ((size_t)(b * 12 + h) * 49) * 32;

    for (int f = tid; f < 392; f += 128) {
        const int row = f >> 3;
        const int c4 = (f & 7) << 2;
        float4 a = *(const float4*)(Qb + row * 32 + c4);
        sq[row][c4] = a.x; sq[row][c4 + 1] = a.y; sq[row][c4 + 2] = a.z; sq[row][c4 + 3] = a.w;
        float4 kk = *(const float4*)(Kb + row * 32 + c4);
        skT[c4][row] = kk.x; skT[c4 + 1][row] = kk.y; skT[c4 + 2][row] = kk.z; skT[c4 + 3][row] = kk.w;
        float4 vv = *(const float4*)(Vb + row * 32 + c4);
        sv[row][c4] = vv.x; sv[row][c4 + 1] = vv.y; sv[row][c4 + 2] = vv.z; sv[row][c4 + 3] = vv.w;
    }
    __syncthreads();

    const int lane2 = lane + 32;
    const bool has2 = lane2 < 49;
    const int m2 = has2 ? lane2 : 0;
    const float* bm = g_BM + ((size_t)(b & 63) * 12 + h) * 2401;

    p1_block<7>(0, warp, lane, m2, has2, sq, skT, ss, bm);
    p1_block<6>(7, warp, lane, m2, has2, sq, skT, ss, bm);
    __syncthreads();

    for (int n = warp; n < 49; n += 4) {
        const float x0 = ss[n][lane];
        const float x1 = has2 ? ss[n][lane2] : -3.0e38f;
        float mx = fmaxf(x0, x1);
#pragma unroll
        for (int o = 16; o; o >>= 1) mx = fmaxf(mx, __shfl_xor_sync(0xffffffffu, mx, o));
        const float e0 = __expf(x0 - mx);
        const float e1 = has2 ? __expf(x1 - mx) : 0.f;
        float sm = e0 + e1;
#pragma unroll
        for (int o = 16; o; o >>= 1) sm += __shfl_xor_sync(0xffffffffu, sm, o);
        const float inv = 1.f / sm;
        ss[n][lane] = e0 * inv;
        if (has2) ss[n][lane2] = e1 * inv;
    }
    __syncthreads();

    __half* AOb = g_AOh + (size_t)(b * 49) * 384 + h * 32 + lane;
    p3_block<7>(0, warp, lane, sv, ss, AOb);
    p3_block<6>(7, warp, lane, sv, ss, AOb);
}

// ---------------------------------------------------------------------------
extern "C" void kernel_launch(void* const* d_in, const int* in_sizes, int n_in,
                              void* d_out, int out_size) {
    const float* x          = (const float*)d_in[0];
    const float* mask       = (const float*)d_in[1];
    const float* qkv_w      = (const float*)d_in[2];
    const float* qkv_b      = (const float*)d_in[3];
    const float* proj_w     = (const float*)d_in[4];
    const float* proj_b     = (const float*)d_in[5];
    const float* bias_table = (const float*)d_in[6];
    const int*   rel_idx    = (const int*)d_in[7];
    float*       out        = (float*)d_out;

    cudaFuncSetAttribute(gemm_h<0>, cudaFuncAttributeMaxDynamicSharedMemorySize, DYNSZ);
    cudaFuncSetAttribute(gemm_h<1>, cudaFuncAttributeMaxDynamicSharedMemorySize, DYNSZ);

    prep_xh<<<37632, 256>>>(x);
    prep_wth<0><<<1152, 384>>>(qkv_w);
    prep_wth<1><<<384, 384>>>(proj_w);
    prep_bm<<<dim3(NWIN, HEADS), 256>>>(mask, bias_table, rel_idx);

    // QKV: cols fastest so A stripes are L2-resident across col blocks
    gemm_h<0><<<dim3(9, 392), 512, DYNSZ>>>(qkv_b, nullptr);

    attn_kernel<<<dim3(2048, 12), 128>>>();

    gemm_h<1><<<dim3(3, 392), 512, DYNSZ>>>(proj_b, out);
}

// round 5
// speedup vs baseline: 1.6794x; 1.1410x over previous
#include <cuda_runtime.h>
#include <cuda_fp16.h>
#include <cstdint>

#define BW    2048
#define NTOK  49
#define CDIM  384
#define HEADS 12
#define HD    32
#define NWIN  64

// ---------------------------------------------------------------------------
// Device scratch (allocation-free)
// ---------------------------------------------------------------------------
__device__ __half g_Xh [BW * NTOK * CDIM];          // x, fp16
__device__ __half g_AOh[BW * NTOK * CDIM];          // attention output, fp16
__device__ __half g_W1h[1152 * 384];                // qkv_w^T  [n][k] fp16
__device__ __half g_W2h[384 * 384];                 // proj_w^T [n][k] fp16
__device__ __half g_Qh[BW * HEADS * NTOK * HD];     // fp16, pre-scaled
__device__ __half g_Kh[BW * HEADS * NTOK * HD];
__device__ __half g_Vh[BW * HEADS * NTOK * HD];
__device__ float  g_BM[NWIN * HEADS * NTOK * NTOK]; // bias[rel_idx] + mask

// ---------------------------------------------------------------------------
// Helpers
// ---------------------------------------------------------------------------
__device__ __forceinline__ uint32_t s2u(const void* p) {
    uint32_t a;
    asm("{ .reg .u64 t; cvta.to.shared.u64 t, %1; cvt.u32.u64 %0, t; }"
        : "=r"(a) : "l"(p));
    return a;
}

__device__ __forceinline__ void cp16(uint32_t saddr, const void* g) {
    asm volatile("cp.async.cg.shared.global [%0], [%1], 16;"
                 :: "r"(saddr), "l"(g) : "memory");
}
__device__ __forceinline__ void cp_commit() {
    asm volatile("cp.async.commit_group;" ::: "memory");
}
template <int N>
__device__ __forceinline__ void cp_wait() {
    asm volatile("cp.async.wait_group %0;" :: "n"(N) : "memory");
}

__device__ __forceinline__ void mma16(float* cc, const unsigned* a, const unsigned* b) {
    asm volatile(
        "mma.sync.aligned.m16n8k16.row.col.f32.f16.f16.f32 "
        "{%0,%1,%2,%3}, {%4,%5,%6,%7}, {%8,%9}, {%0,%1,%2,%3};"
        : "+f"(cc[0]), "+f"(cc[1]), "+f"(cc[2]), "+f"(cc[3])
        : "r"(a[0]), "r"(a[1]), "r"(a[2]), "r"(a[3]), "r"(b[0]), "r"(b[1]));
}

// ---------------------------------------------------------------------------
// Prep kernels
// ---------------------------------------------------------------------------
__global__ void __launch_bounds__(256) prep_xh(const float* __restrict__ x) {
    const int i = blockIdx.x * 256 + threadIdx.x;
    float4 v = ((const float4*)x)[i];
    __half2* dst = (__half2*)g_Xh;
    dst[2 * i]     = __floats2half2_rn(v.x, v.y);
    dst[2 * i + 1] = __floats2half2_rn(v.z, v.w);
}

template <int WHICH>
__global__ void __launch_bounds__(384) prep_wth(const float* __restrict__ w) {
    const int N = WHICH ? 384 : 1152;
    __half* wt = WHICH ? g_W2h : g_W1h;
    const int n = blockIdx.x;
    const int k = threadIdx.x;
    wt[n * 384 + k] = __float2half_rn(w[k * N + n]);
}

__global__ void __launch_bounds__(256) prep_bm(const float* __restrict__ mask,
                                               const float* __restrict__ bt,
                                               const int* __restrict__ ri) {
    const int w = blockIdx.x, h = blockIdx.y;
    float* dst = g_BM + (w * HEADS + h) * (NTOK * NTOK);
    const float* mw = mask + w * (NTOK * NTOK);
    for (int i = threadIdx.x; i < NTOK * NTOK; i += 256)
        dst[i] = bt[ri[i] * HEADS + h] + mw[i];
}

// ---------------------------------------------------------------------------
// fp16 mma.sync GEMM with cp.async 3-stage pipeline (same core as R4-pass).
// Epilogue now writes Q/K/V as fp16.
// ---------------------------------------------------------------------------
#define STG_B  24576
#define STG_U  6144
#define NSTG   3
#define DYNSZ  (NSTG * STG_B)

template <int EPI>
__global__ void __launch_bounds__(512) gemm_h(const float* __restrict__ bias,
                                              float* __restrict__ out) {
    extern __shared__ char smem[];
    const uint32_t smem0 = s2u(smem);
    const unsigned* SU = (const unsigned*)smem;

    const __half* A  = (EPI == 0) ? g_Xh : g_AOh;
    const __half* Bw = (EPI == 0) ? (const __half*)g_W1h : (const __half*)g_W2h;

    const int tid  = threadIdx.x;
    const int lane = tid & 31;
    const int warp = tid >> 5;
    const int wm   = warp >> 2;
    const int wn   = warp & 3;
    const int colBase = blockIdx.x * 128;
    const int rowBase = blockIdx.y * 256;

    const __half* Ag = A + (size_t)rowBase * 384;
    const __half* Bg = Bw + (size_t)colBase * 384;

    const int am0 = tid >> 2,          ac0 = tid & 3;
    const int am1 = (tid + 512) >> 2,  ac1 = (tid + 512) & 3;
    const int bn  = tid >> 2,          bc  = tid & 3;

#define LOADSTG(s, kt)                                                          \
    do {                                                                        \
        const uint32_t sb = smem0 + (s) * STG_B;                                \
        cp16(sb + ac0 * 4096 + am0 * 16, Ag + am0 * 384 + (kt) * 32 + ac0 * 8); \
        cp16(sb + ac1 * 4096 + am1 * 16, Ag + am1 * 384 + (kt) * 32 + ac1 * 8); \
        cp16(sb + 16384 + bc * 2048 + bn * 16,                                  \
             Bg + bn * 384 + (kt) * 32 + bc * 8);                               \
    } while (0)

    float acc[4][4][4];
#pragma unroll
    for (int mi = 0; mi < 4; mi++)
#pragma unroll
        for (int ni = 0; ni < 4; ni++)
#pragma unroll
            for (int k = 0; k < 4; k++) acc[mi][ni][k] = 0.f;

    LOADSTG(0, 0);
    cp_commit();
    LOADSTG(1, 1);
    cp_commit();

    const int r = lane >> 2;
    const int c = lane & 3;

    for (int kt = 0; kt < 12; kt++) {
        if (kt < 11) cp_wait<1>(); else cp_wait<0>();
        __syncthreads();
        if (kt + 2 < 12) { LOADSTG((kt + 2) % NSTG, kt + 2); cp_commit(); }

        const unsigned* SA = SU + (kt % NSTG) * STG_U;
        const unsigned* SB = SA + 4096;
#pragma unroll
        for (int ks = 0; ks < 2; ks++) {
            unsigned af[4][4], bf[4][2];
#pragma unroll
            for (int mi = 0; mi < 4; mi++) {
                const int m0 = wm * 64 + mi * 16 + r;
                af[mi][0] = SA[(2 * ks) * 1024 + m0 * 4 + c];
                af[mi][1] = SA[(2 * ks) * 1024 + (m0 + 8) * 4 + c];
                af[mi][2] = SA[(2 * ks + 1) * 1024 + m0 * 4 + c];
                af[mi][3] = SA[(2 * ks + 1) * 1024 + (m0 + 8) * 4 + c];
            }
#pragma unroll
            for (int ni = 0; ni < 4; ni++) {
                const int n0 = wn * 32 + ni * 8 + r;
                bf[ni][0] = SB[(2 * ks) * 512 + n0 * 4 + c];
                bf[ni][1] = SB[(2 * ks + 1) * 512 + n0 * 4 + c];
            }
#pragma unroll
            for (int mi = 0; mi < 4; mi++)
#pragma unroll
                for (int ni = 0; ni < 4; ni++) mma16(acc[mi][ni], af[mi], bf[ni]);
        }
        __syncthreads();
    }

    // -------- epilogue
#pragma unroll
    for (int mi = 0; mi < 4; mi++) {
#pragma unroll
        for (int g = 0; g < 2; g++) {
            const int row = rowBase + wm * 64 + mi * 16 + r + g * 8;
            int bb = 0, n = 0;
            if (EPI == 0) { bb = row / 49; n = row - bb * 49; }
#pragma unroll
            for (int ni = 0; ni < 4; ni++) {
                const int col = colBase + wn * 32 + ni * 8 + 2 * c;
                float2 b2 = *(const float2*)(bias + col);
                float2 v;
                v.x = acc[mi][ni][g * 2 + 0] + b2.x;
                v.y = acc[mi][ni][g * 2 + 1] + b2.y;
                if (EPI == 0) {
                    const int which = (col >= 768) ? 2 : (col >= 384 ? 1 : 0);
                    const int ccc = col - which * 384;
                    const int h = ccc >> 5, dd = ccc & 31;
                    const size_t di = ((size_t)(bb * 12 + h) * 49 + n) * 32 + dd;
                    if (which == 0) {
                        v.x *= 0.17677669529663689f;
                        v.y *= 0.17677669529663689f;
                        *(__half2*)(g_Qh + di) = __floats2half2_rn(v.x, v.y);
                    } else if (which == 1) {
                        *(__half2*)(g_Kh + di) = __floats2half2_rn(v.x, v.y);
                    } else {
                        *(__half2*)(g_Vh + di) = __floats2half2_rn(v.x, v.y);
                    }
                } else {
                    *(float2*)(out + (size_t)row * 384 + col) = v;
                }
            }
        }
    }
#undef LOADSTG
}

// ---------------------------------------------------------------------------
// Tensor-core attention: one CTA (128 threads = 4 warps) per (window b, head h)
// S = Q Kt (padded 64x64), + bias+mask, softmax, O = P V via mma.m16n8k16.
// ---------------------------------------------------------------------------
#define SQK_STR 40   // halfs per row (banks: 20r+c all distinct)
#define SVT_STR 72
#define SS_STR  68
#define SP_STR  72

__global__ void __launch_bounds__(128) attn_mma() {
    __shared__ __half sQ[64 * SQK_STR];
    __shared__ __half sK[64 * SQK_STR];
    __shared__ __half sVT[32 * SVT_STR];
    __shared__ float  sS[64 * SS_STR];
    __shared__ __half sP[64 * SP_STR];

    const int b = blockIdx.x;
    const int h = blockIdx.y;
    const int tid = threadIdx.x;
    const int lane = tid & 31;
    const int warp = tid >> 5;

    const __half* Qb = g_Qh + (size_t)(b * 12 + h) * 1568;
    const __half* Kb = g_Kh + (size_t)(b * 12 + h) * 1568;
    const __half* Vb = g_Vh + (size_t)(b * 12 + h) * 1568;

    // zero pad rows 49..63 of Q,K (uints: rows at 49*20, 300 uints each)
    for (int i = tid; i < 300; i += 128) {
        ((unsigned*)sQ)[980 + i] = 0u;
        ((unsigned*)sK)[980 + i] = 0u;
    }
    // zero VT pad cols m=49..63 (15 cols x 32 rows) — disjoint from loads
    for (int i = tid; i < 480; i += 128) {
        const int d = i / 15, m = 49 + i % 15;
        sVT[d * SVT_STR + m] = __ushort_as_half(0);
    }

    // load Q,K row-major; V transposed
    for (int f = tid; f < 196; f += 128) {
        const int row = f >> 2, ch = (f & 3) * 8;
        *(uint4*)&sQ[row * SQK_STR + ch] = *(const uint4*)(Qb + row * 32 + ch);
        *(uint4*)&sK[row * SQK_STR + ch] = *(const uint4*)(Kb + row * 32 + ch);
        union { uint4 u; __half hh[8]; } vv;
        vv.u = *(const uint4*)(Vb + row * 32 + ch);
#pragma unroll
        for (int j = 0; j < 8; j++) sVT[(ch + j) * SVT_STR + row] = vv.hh[j];
    }
    __syncthreads();

    const int r = lane >> 2, c = lane & 3;
    const float* bm = g_BM + ((size_t)(b & 63) * 12 + h) * 2401;

    // ---- Phase 1: S = Q Kt (+bias+mask). Warp n-strip = 16 cols.
    const int n0w = warp * 16;
#pragma unroll
    for (int mi = 0; mi < 4; mi++) {
        const int m0 = mi * 16;
        unsigned a[2][4];
#pragma unroll
        for (int ks = 0; ks < 2; ks++) {
            const __half* ab = &sQ[(m0 + r) * SQK_STR + ks * 16 + 2 * c];
            a[ks][0] = *(const unsigned*)ab;
            a[ks][1] = *(const unsigned*)(ab + 8 * SQK_STR);
            a[ks][2] = *(const unsigned*)(ab + 8);
            a[ks][3] = *(const unsigned*)(ab + 8 * SQK_STR + 8);
        }
#pragma unroll
        for (int ni = 0; ni < 2; ni++) {
            const int n0 = n0w + ni * 8;
            float acc[4] = {0.f, 0.f, 0.f, 0.f};
#pragma unroll
            for (int ks = 0; ks < 2; ks++) {
                unsigned bfr[2];
                const __half* bb = &sK[(n0 + r) * SQK_STR + ks * 16 + 2 * c];
                bfr[0] = *(const unsigned*)bb;
                bfr[1] = *(const unsigned*)(bb + 8);
                mma16(acc, a[ks], bfr);
            }
            const int row0 = m0 + r;
            const int col = n0 + 2 * c;
            const int rc0 = (row0 < 49 ? row0 : 48) * 49;
            const int rc1 = (row0 + 8 < 49 ? row0 + 8 : 48) * 49;
            sS[row0 * SS_STR + col]     = (col < 49)     ? acc[0] + bm[rc0 + col]     : -1e30f;
            sS[row0 * SS_STR + col + 1] = (col + 1 < 49) ? acc[1] + bm[rc0 + col + 1] : -1e30f;
            sS[(row0 + 8) * SS_STR + col]     = (col < 49)     ? acc[2] + bm[rc1 + col]     : -1e30f;
            sS[(row0 + 8) * SS_STR + col + 1] = (col + 1 < 49) ? acc[3] + bm[rc1 + col + 1] : -1e30f;
        }
    }
    __syncthreads();

    // ---- Phase 2: softmax, warp-per-row (cols >=49 hold -1e30 -> exp 0)
    for (int n = warp; n < 49; n += 4) {
        const float x0 = sS[n * SS_STR + lane];
        const float x1 = sS[n * SS_STR + lane + 32];
        float mx = fmaxf(x0, x1);
#pragma unroll
        for (int o = 16; o; o >>= 1) mx = fmaxf(mx, __shfl_xor_sync(0xffffffffu, mx, o));
        const float e0 = __expf(x0 - mx);
        const float e1 = __expf(x1 - mx);
        float sm = e0 + e1;
#pragma unroll
        for (int o = 16; o; o >>= 1) sm += __shfl_xor_sync(0xffffffffu, sm, o);
        const float inv = 1.f / sm;
        sS[n * SS_STR + lane] = e0 * inv;
        sS[n * SS_STR + lane + 32] = e1 * inv;
    }
    __syncthreads();

    // ---- convert P to fp16 (rows < 49; pad rows feed only unwritten outputs)
    for (int idx = tid; idx < 49 * 32; idx += 128) {
        const int row = idx >> 5, cp = (idx & 31) * 2;
        *(__half2*)&sP[row * SP_STR + cp] =
            __floats2half2_rn(sS[row * SS_STR + cp], sS[row * SS_STR + cp + 1]);
    }
    // zero P pad rows so no stray NaN/inf reaches HMMA scheduling
    for (int i = tid; i < 15 * 32; i += 128) {
        const int row = 49 + i / 32, cp = (i & 31) * 2;
        *(__half2*)&sP[row * SP_STR + cp] = __floats2half2_rn(0.f, 0.f);
    }
    __syncthreads();

    // ---- Phase 3: O = P V. Warp d-strip = 8 cols.
    const int d0 = warp * 8;
    __half* AOb = g_AOh + (size_t)b * 49 * 384 + h * 32;
#pragma unroll
    for (int mi = 0; mi < 4; mi++) {
        const int m0 = mi * 16;
        float acc[4] = {0.f, 0.f, 0.f, 0.f};
#pragma unroll
        for (int ks = 0; ks < 4; ks++) {
            unsigned a[4], bfr[2];
            const __half* ab = &sP[(m0 + r) * SP_STR + ks * 16 + 2 * c];
            a[0] = *(const unsigned*)ab;
            a[1] = *(const unsigned*)(ab + 8 * SP_STR);
            a[2] = *(const unsigned*)(ab + 8);
            a[3] = *(const unsigned*)(ab + 8 * SP_STR + 8);
            const __half* bb = &sVT[(d0 + r) * SVT_STR + ks * 16 + 2 * c];
            bfr[0] = *(const unsigned*)bb;
            bfr[1] = *(const unsigned*)(bb + 8);
            mma16(acc, a, bfr);
        }
        const int row0 = m0 + r, col = d0 + 2 * c;
        if (row0 < 49)
            *(__half2*)&AOb[row0 * 384 + col] = __floats2half2_rn(acc[0], acc[1]);
        if (row0 + 8 < 49)
            *(__half2*)&AOb[(row0 + 8) * 384 + col] = __floats2half2_rn(acc[2], acc[3]);
    }
}

// ---------------------------------------------------------------------------
extern "C" void kernel_launch(void* const* d_in, const int* in_sizes, int n_in,
                              void* d_out, int out_size) {
    const float* x          = (const float*)d_in[0];
    const float* mask       = (const float*)d_in[1];
    const float* qkv_w      = (const float*)d_in[2];
    const float* qkv_b      = (const float*)d_in[3];
    const float* proj_w     = (const float*)d_in[4];
    const float* proj_b     = (const float*)d_in[5];
    const float* bias_table = (const float*)d_in[6];
    const int*   rel_idx    = (const int*)d_in[7];
    float*       out        = (float*)d_out;

    cudaFuncSetAttribute(gemm_h<0>, cudaFuncAttributeMaxDynamicSharedMemorySize, DYNSZ);
    cudaFuncSetAttribute(gemm_h<1>, cudaFuncAttributeMaxDynamicSharedMemorySize, DYNSZ);

    prep_xh<<<37632, 256>>>(x);
    prep_wth<0><<<1152, 384>>>(qkv_w);
    prep_wth<1><<<384, 384>>>(proj_w);
    prep_bm<<<dim3(NWIN, HEADS), 256>>>(mask, bias_table, rel_idx);

    gemm_h<0><<<dim3(9, 392), 512, DYNSZ>>>(qkv_b, nullptr);

    attn_mma<<<dim3(2048, 12), 128>>>();

    gemm_h<1><<<dim3(3, 392), 512, DYNSZ>>>(proj_b, out);
}

// round 6
// speedup vs baseline: 1.9013x; 1.1321x over previous
#include <cuda_runtime.h>
#include <cuda_fp16.h>
#include <cstdint>

#define BW    2048
#define NTOK  49
#define CDIM  384
#define HEADS 12
#define HD    32
#define NWIN  64

// ---------------------------------------------------------------------------
// Device scratch (allocation-free)
// ---------------------------------------------------------------------------
__device__ __half g_Xh [BW * NTOK * CDIM];          // x, fp16
__device__ __half g_AOh[BW * NTOK * CDIM];          // attention output, fp16
__device__ __half g_W1h[1152 * 384];                // qkv_w^T  [n][k] fp16
__device__ __half g_W2h[384 * 384];                 // proj_w^T [n][k] fp16
__device__ __half g_Qh[BW * HEADS * NTOK * HD];     // fp16, pre-scaled
__device__ __half g_Kh[BW * HEADS * NTOK * HD];
__device__ __half g_Vh[BW * HEADS * NTOK * HD];
__device__ float  g_BM[NWIN * HEADS * NTOK * NTOK]; // bias[rel_idx] + mask

// ---------------------------------------------------------------------------
// Helpers
// ---------------------------------------------------------------------------
__device__ __forceinline__ uint32_t s2u(const void* p) {
    uint32_t a;
    asm("{ .reg .u64 t; cvta.to.shared.u64 t, %1; cvt.u32.u64 %0, t; }"
        : "=r"(a) : "l"(p));
    return a;
}

__device__ __forceinline__ void cp16(uint32_t saddr, const void* g) {
    asm volatile("cp.async.cg.shared.global [%0], [%1], 16;"
                 :: "r"(saddr), "l"(g) : "memory");
}
__device__ __forceinline__ void cp_commit() {
    asm volatile("cp.async.commit_group;" ::: "memory");
}
template <int N>
__device__ __forceinline__ void cp_wait() {
    asm volatile("cp.async.wait_group %0;" :: "n"(N) : "memory");
}

__device__ __forceinline__ void mma16(float* cc, const unsigned* a, const unsigned* b) {
    asm volatile(
        "mma.sync.aligned.m16n8k16.row.col.f32.f16.f16.f32 "
        "{%0,%1,%2,%3}, {%4,%5,%6,%7}, {%8,%9}, {%0,%1,%2,%3};"
        : "+f"(cc[0]), "+f"(cc[1]), "+f"(cc[2]), "+f"(cc[3])
        : "r"(a[0]), "r"(a[1]), "r"(a[2]), "r"(a[3]), "r"(b[0]), "r"(b[1]));
}

__device__ __forceinline__ void ldsm4(unsigned* d, uint32_t a) {
    asm volatile("ldmatrix.sync.aligned.m8n8.x4.shared.b16 {%0,%1,%2,%3}, [%4];"
                 : "=r"(d[0]), "=r"(d[1]), "=r"(d[2]), "=r"(d[3]) : "r"(a));
}
__device__ __forceinline__ void ldsm2t(unsigned* d, uint32_t a) {
    asm volatile("ldmatrix.sync.aligned.m8n8.x2.trans.shared.b16 {%0,%1}, [%2];"
                 : "=r"(d[0]), "=r"(d[1]) : "r"(a));
}

// ---------------------------------------------------------------------------
// Prep kernels
// ---------------------------------------------------------------------------
__global__ void __launch_bounds__(256) prep_xh(const float* __restrict__ x) {
    const int i = blockIdx.x * 256 + threadIdx.x;
    float4 v = ((const float4*)x)[i];
    __half2* dst = (__half2*)g_Xh;
    dst[2 * i]     = __floats2half2_rn(v.x, v.y);
    dst[2 * i + 1] = __floats2half2_rn(v.z, v.w);
}

template <int WHICH>
__global__ void __launch_bounds__(384) prep_wth(const float* __restrict__ w) {
    const int N = WHICH ? 384 : 1152;
    __half* wt = WHICH ? g_W2h : g_W1h;
    const int n = blockIdx.x;
    const int k = threadIdx.x;
    wt[n * 384 + k] = __float2half_rn(w[k * N + n]);
}

__global__ void __launch_bounds__(256) prep_bm(const float* __restrict__ mask,
                                               const float* __restrict__ bt,
                                               const int* __restrict__ ri) {
    const int w = blockIdx.x, h = blockIdx.y;
    float* dst = g_BM + (w * HEADS + h) * (NTOK * NTOK);
    const float* mw = mask + w * (NTOK * NTOK);
    for (int i = threadIdx.x; i < NTOK * NTOK; i += 256)
        dst[i] = bt[ri[i] * HEADS + h] + mw[i];
}

// ---------------------------------------------------------------------------
// fp16 mma.sync GEMM, cp.async 3-stage pipeline, ldmatrix fragment feeds.
// ---------------------------------------------------------------------------
#define STG_B  24576
#define NSTG   3
#define DYNSZ  (NSTG * STG_B)

template <int EPI>
__global__ void __launch_bounds__(512) gemm_h(const float* __restrict__ bias,
                                              float* __restrict__ out) {
    extern __shared__ char smem[];
    const uint32_t smem0 = s2u(smem);

    const __half* A  = (EPI == 0) ? g_Xh : g_AOh;
    const __half* Bw = (EPI == 0) ? (const __half*)g_W1h : (const __half*)g_W2h;

    const int tid  = threadIdx.x;
    const int lane = tid & 31;
    const int warp = tid >> 5;
    const int wm   = warp >> 2;
    const int wn   = warp & 3;
    const int colBase = blockIdx.x * 128;
    const int rowBase = blockIdx.y * 256;

    const __half* Ag = A + (size_t)rowBase * 384;
    const __half* Bg = Bw + (size_t)colBase * 384;

    const int am0 = tid >> 2,          ac0 = tid & 3;
    const int am1 = (tid + 512) >> 2,  ac1 = (tid + 512) & 3;
    const int bn  = tid >> 2,          bc  = tid & 3;

#define LOADSTG(s, kt)                                                          \
    do {                                                                        \
        const uint32_t sb = smem0 + (s) * STG_B;                                \
        cp16(sb + ac0 * 4096 + am0 * 16, Ag + am0 * 384 + (kt) * 32 + ac0 * 8); \
        cp16(sb + ac1 * 4096 + am1 * 16, Ag + am1 * 384 + (kt) * 32 + ac1 * 8); \
        cp16(sb + 16384 + bc * 2048 + bn * 16,                                  \
             Bg + bn * 384 + (kt) * 32 + bc * 8);                               \
    } while (0)

    float acc[4][4][4];
#pragma unroll
    for (int mi = 0; mi < 4; mi++)
#pragma unroll
        for (int ni = 0; ni < 4; ni++)
#pragma unroll
            for (int k = 0; k < 4; k++) acc[mi][ni][k] = 0.f;

    LOADSTG(0, 0);
    cp_commit();
    LOADSTG(1, 1);
    cp_commit();

    const int r = lane >> 2;
    const int c = lane & 3;
    const int lr = lane & 7, sel = lane >> 3;
    // ldmatrix lane-invariant offsets
    const uint32_t a_lane = (uint32_t)((lr + (sel & 1) * 8) * 16 + (sel >> 1) * 4096);
    const uint32_t b_lane = (uint32_t)(((sel >> 1) * 8 + lr) * 16 + (sel & 1) * 2048);

    for (int kt = 0; kt < 12; kt++) {
        if (kt < 11) cp_wait<1>(); else cp_wait<0>();
        __syncthreads();
        if (kt + 2 < 12) { LOADSTG((kt + 2) % NSTG, kt + 2); cp_commit(); }

        const uint32_t sb = smem0 + (kt % NSTG) * STG_B;
#pragma unroll
        for (int ks = 0; ks < 2; ks++) {
            unsigned af[4][4], bf[4][2];
#pragma unroll
            for (int mi = 0; mi < 4; mi++)
                ldsm4(af[mi], sb + (2 * ks) * 4096 + (wm * 64 + mi * 16) * 16 + a_lane);
#pragma unroll
            for (int p = 0; p < 2; p++) {
                unsigned t[4];
                ldsm4(t, sb + 16384 + (2 * ks) * 2048 + (wn * 32 + p * 16) * 16 + b_lane);
                bf[2 * p][0] = t[0]; bf[2 * p][1] = t[1];
                bf[2 * p + 1][0] = t[2]; bf[2 * p + 1][1] = t[3];
            }
#pragma unroll
            for (int mi = 0; mi < 4; mi++)
#pragma unroll
                for (int ni = 0; ni < 4; ni++) mma16(acc[mi][ni], af[mi], bf[ni]);
        }
        __syncthreads();
    }

    // -------- epilogue
#pragma unroll
    for (int mi = 0; mi < 4; mi++) {
#pragma unroll
        for (int g = 0; g < 2; g++) {
            const int row = rowBase + wm * 64 + mi * 16 + r + g * 8;
            int bb = 0, n = 0;
            if (EPI == 0) { bb = row / 49; n = row - bb * 49; }
#pragma unroll
            for (int ni = 0; ni < 4; ni++) {
                const int col = colBase + wn * 32 + ni * 8 + 2 * c;
                float2 b2 = *(const float2*)(bias + col);
                float2 v;
                v.x = acc[mi][ni][g * 2 + 0] + b2.x;
                v.y = acc[mi][ni][g * 2 + 1] + b2.y;
                if (EPI == 0) {
                    const int which = (col >= 768) ? 2 : (col >= 384 ? 1 : 0);
                    const int ccc = col - which * 384;
                    const int h = ccc >> 5, dd = ccc & 31;
                    const size_t di = ((size_t)(bb * 12 + h) * 49 + n) * 32 + dd;
                    if (which == 0) {
                        v.x *= 0.17677669529663689f;
                        v.y *= 0.17677669529663689f;
                        *(__half2*)(g_Qh + di) = __floats2half2_rn(v.x, v.y);
                    } else if (which == 1) {
                        *(__half2*)(g_Kh + di) = __floats2half2_rn(v.x, v.y);
                    } else {
                        *(__half2*)(g_Vh + di) = __floats2half2_rn(v.x, v.y);
                    }
                } else {
                    *(float2*)(out + (size_t)row * 384 + col) = v;
                }
            }
        }
    }
#undef LOADSTG
}

// ---------------------------------------------------------------------------
// Tensor-core attention with ldmatrix feeds.
// One CTA (128 threads = 4 warps) per (window b, head h).
// ---------------------------------------------------------------------------
#define AQ_STR 40   // halfs per row for sQ/sK/sV (80B; ldmatrix banks 20r: distinct)
#define AS_STR 68   // floats per row for sS
#define AP_STR 72   // halfs per row for sP (144B; ldmatrix banks 4r: distinct)

__global__ void __launch_bounds__(128) attn_mma() {
    __shared__ __half sQ[64 * AQ_STR];
    __shared__ __half sK[64 * AQ_STR];
    __shared__ __half sV[64 * AQ_STR];
    __shared__ float  sS[64 * AS_STR];
    __shared__ __half sP[64 * AP_STR];

    const int b = blockIdx.x;
    const int h = blockIdx.y;
    const int tid = threadIdx.x;
    const int lane = tid & 31;
    const int warp = tid >> 5;

    const __half* Qb = g_Qh + (size_t)(b * 12 + h) * 1568;
    const __half* Kb = g_Kh + (size_t)(b * 12 + h) * 1568;
    const __half* Vb = g_Vh + (size_t)(b * 12 + h) * 1568;

    // zero V pad rows 49..63 (0 x NaN hazard); Q/K pad garbage is harmless.
    {
        uint4 z = {0u, 0u, 0u, 0u};
        uint4* vp = (uint4*)(sV + 49 * AQ_STR);   // 15*40 halfs = 75 uint4
        for (int i = tid; i < 75; i += 128) vp[i] = z;
    }

    // load Q,K,V row-major (vectorized)
    for (int f = tid; f < 196; f += 128) {
        const int row = f >> 2, ch = (f & 3) * 8;
        *(uint4*)&sQ[row * AQ_STR + ch] = *(const uint4*)(Qb + row * 32 + ch);
        *(uint4*)&sK[row * AQ_STR + ch] = *(const uint4*)(Kb + row * 32 + ch);
        *(uint4*)&sV[row * AQ_STR + ch] = *(const uint4*)(Vb + row * 32 + ch);
    }
    __syncthreads();

    const int r = lane >> 2, c = lane & 3;
    const int lr = lane & 7, sel = lane >> 3;
    const float* bm = g_BM + ((size_t)(b & 63) * 12 + h) * 2401;

    const uint32_t sQb = s2u(sQ), sKb = s2u(sK), sVb = s2u(sV), sPb = s2u(sP);
    const uint32_t qp_lane80  = (uint32_t)((lr + (sel & 1) * 8) * 80 + (sel >> 1) * 16);
    const uint32_t k_lane80   = (uint32_t)((((sel >> 1) * 8) + lr) * 80 + (sel & 1) * 16);
    const uint32_t p_lane144  = (uint32_t)((lr + (sel & 1) * 8) * 144 + (sel >> 1) * 16);
    const uint32_t v_lane80   = (uint32_t)((lr + ((lane >> 3) & 1) * 8) * 80);

    // ---- Phase 1: S = Q Kt (+bias+mask). Warp n-strip = 16 cols.
    const int n0w = warp * 16;
    unsigned bK[2][4];
#pragma unroll
    for (int ks = 0; ks < 2; ks++)
        ldsm4(bK[ks], sKb + n0w * 80 + ks * 32 + k_lane80);

#pragma unroll
    for (int mi = 0; mi < 4; mi++) {
        const int m0 = mi * 16;
        unsigned aQ[2][4];
#pragma unroll
        for (int ks = 0; ks < 2; ks++)
            ldsm4(aQ[ks], sQb + m0 * 80 + ks * 32 + qp_lane80);
#pragma unroll
        for (int ni = 0; ni < 2; ni++) {
            float acc[4] = {0.f, 0.f, 0.f, 0.f};
#pragma unroll
            for (int ks = 0; ks < 2; ks++) mma16(acc, aQ[ks], &bK[ks][2 * ni]);
            const int row0 = m0 + r;
            const int col = n0w + ni * 8 + 2 * c;
            const int rc0 = (row0 < 49 ? row0 : 48) * 49;
            const int rc1 = (row0 + 8 < 49 ? row0 + 8 : 48) * 49;
            sS[row0 * AS_STR + col]     = (col < 49)     ? acc[0] + bm[rc0 + col]     : -1e30f;
            sS[row0 * AS_STR + col + 1] = (col + 1 < 49) ? acc[1] + bm[rc0 + col + 1] : -1e30f;
            sS[(row0 + 8) * AS_STR + col]     = (col < 49)     ? acc[2] + bm[rc1 + col]     : -1e30f;
            sS[(row0 + 8) * AS_STR + col + 1] = (col + 1 < 49) ? acc[3] + bm[rc1 + col + 1] : -1e30f;
        }
    }
    __syncthreads();

    // ---- Phase 2: softmax (warp per row), write P directly as fp16.
    for (int n = warp; n < 49; n += 4) {
        const float x0 = sS[n * AS_STR + lane];
        const float x1 = sS[n * AS_STR + lane + 32];
        float mx = fmaxf(x0, x1);
#pragma unroll
        for (int o = 16; o; o >>= 1) mx = fmaxf(mx, __shfl_xor_sync(0xffffffffu, mx, o));
        const float e0 = __expf(x0 - mx);
        const float e1 = __expf(x1 - mx);
        float sm = e0 + e1;
#pragma unroll
        for (int o = 16; o; o >>= 1) sm += __shfl_xor_sync(0xffffffffu, sm, o);
        const float inv = 1.f / sm;
        sP[n * AP_STR + lane]      = __float2half_rn(e0 * inv);
        sP[n * AP_STR + lane + 32] = __float2half_rn(e1 * inv);
    }
    // P pad rows 49..63 stay garbage: they only feed discarded output rows,
    // and P pad COLS (k>=49) are exact zeros from exp(-1e30), so V-side NaN
    // cannot enter valid rows (V pad rows zeroed above).
    __syncthreads();

    // ---- Phase 3: O = P V. Warp d-strip = 8 cols. V via ldmatrix.trans.
    const int d0 = warp * 8;
    unsigned bV[4][2];
#pragma unroll
    for (int ks = 0; ks < 4; ks++)
        ldsm2t(bV[ks], sVb + (ks * 16) * 80 + v_lane80 + d0 * 2);

    __half* AOb = g_AOh + (size_t)b * 49 * 384 + h * 32;
#pragma unroll
    for (int mi = 0; mi < 4; mi++) {
        const int m0 = mi * 16;
        float acc[4] = {0.f, 0.f, 0.f, 0.f};
#pragma unroll
        for (int ks = 0; ks < 4; ks++) {
            unsigned aP[4];
            ldsm4(aP, sPb + m0 * 144 + ks * 32 + p_lane144);
            mma16(acc, aP, bV[ks]);
        }
        const int row0 = m0 + r, col = d0 + 2 * c;
        if (row0 < 49)
            *(__half2*)&AOb[row0 * 384 + col] = __floats2half2_rn(acc[0], acc[1]);
        if (row0 + 8 < 49)
            *(__half2*)&AOb[(row0 + 8) * 384 + col] = __floats2half2_rn(acc[2], acc[3]);
    }
}

// ---------------------------------------------------------------------------
extern "C" void kernel_launch(void* const* d_in, const int* in_sizes, int n_in,
                              void* d_out, int out_size) {
    const float* x          = (const float*)d_in[0];
    const float* mask       = (const float*)d_in[1];
    const float* qkv_w      = (const float*)d_in[2];
    const float* qkv_b      = (const float*)d_in[3];
    const float* proj_w     = (const float*)d_in[4];
    const float* proj_b     = (const float*)d_in[5];
    const float* bias_table = (const float*)d_in[6];
    const int*   rel_idx    = (const int*)d_in[7];
    float*       out        = (float*)d_out;

    cudaFuncSetAttribute(gemm_h<0>, cudaFuncAttributeMaxDynamicSharedMemorySize, DYNSZ);
    cudaFuncSetAttribute(gemm_h<1>, cudaFuncAttributeMaxDynamicSharedMemorySize, DYNSZ);

    prep_xh<<<37632, 256>>>(x);
    prep_wth<0><<<1152, 384>>>(qkv_w);
    prep_wth<1><<<384, 384>>>(proj_w);
    prep_bm<<<dim3(NWIN, HEADS), 256>>>(mask, bias_table, rel_idx);

    gemm_h<0><<<dim3(9, 392), 512, DYNSZ>>>(qkv_b, nullptr);

    attn_mma<<<dim3(2048, 12), 128>>>();

    gemm_h<1><<<dim3(3, 392), 512, DYNSZ>>>(proj_b, out);
}

// round 7
// speedup vs baseline: 2.2560x; 1.1866x over previous
#include <cuda_runtime.h>
#include <cuda_fp16.h>
#include <cstdint>

#define BW    2048
#define NTOK  49
#define CDIM  384
#define HEADS 12
#define HD    32
#define NWIN  64

// ---------------------------------------------------------------------------
// Device scratch (allocation-free)
// ---------------------------------------------------------------------------
__device__ __half g_Xh [BW * NTOK * CDIM];          // x, fp16
__device__ __half g_AOh[BW * NTOK * CDIM];          // attention output, fp16
__device__ __half g_W1h[1152 * 384];                // qkv_w^T  [n][k] fp16
__device__ __half g_W2h[384 * 384];                 // proj_w^T [n][k] fp16
__device__ __half g_Qh[BW * HEADS * NTOK * HD];     // fp16, pre-scaled
__device__ __half g_Kh[BW * HEADS * NTOK * HD];
__device__ __half g_Vh[BW * HEADS * NTOK * HD];
__device__ float  g_BM[NWIN * HEADS * NTOK * NTOK]; // bias[rel_idx] + mask

// ---------------------------------------------------------------------------
// Helpers
// ---------------------------------------------------------------------------
__device__ __forceinline__ uint32_t s2u(const void* p) {
    uint32_t a;
    asm("{ .reg .u64 t; cvta.to.shared.u64 t, %1; cvt.u32.u64 %0, t; }"
        : "=r"(a) : "l"(p));
    return a;
}

__device__ __forceinline__ void cp16(uint32_t saddr, const void* g) {
    asm volatile("cp.async.cg.shared.global [%0], [%1], 16;"
                 :: "r"(saddr), "l"(g) : "memory");
}
__device__ __forceinline__ void cp_commit() {
    asm volatile("cp.async.commit_group;" ::: "memory");
}
template <int N>
__device__ __forceinline__ void cp_wait() {
    asm volatile("cp.async.wait_group %0;" :: "n"(N) : "memory");
}

__device__ __forceinline__ void mma16(float* cc, const unsigned* a, const unsigned* b) {
    asm volatile(
        "mma.sync.aligned.m16n8k16.row.col.f32.f16.f16.f32 "
        "{%0,%1,%2,%3}, {%4,%5,%6,%7}, {%8,%9}, {%0,%1,%2,%3};"
        : "+f"(cc[0]), "+f"(cc[1]), "+f"(cc[2]), "+f"(cc[3])
        : "r"(a[0]), "r"(a[1]), "r"(a[2]), "r"(a[3]), "r"(b[0]), "r"(b[1]));
}

__device__ __forceinline__ void ldsm4(unsigned* d, uint32_t a) {
    asm volatile("ldmatrix.sync.aligned.m8n8.x4.shared.b16 {%0,%1,%2,%3}, [%4];"
                 : "=r"(d[0]), "=r"(d[1]), "=r"(d[2]), "=r"(d[3]) : "r"(a));
}
__device__ __forceinline__ void ldsm2t(unsigned* d, uint32_t a) {
    asm volatile("ldmatrix.sync.aligned.m8n8.x2.trans.shared.b16 {%0,%1}, [%2];"
                 : "=r"(d[0]), "=r"(d[1]) : "r"(a));
}

__device__ __forceinline__ unsigned pack_h2(float a, float b) {
    __half2 h = __floats2half2_rn(a, b);
    return *reinterpret_cast<unsigned*>(&h);
}

// ---------------------------------------------------------------------------
// Prep kernels
// ---------------------------------------------------------------------------
__global__ void __launch_bounds__(256) prep_xh(const float* __restrict__ x) {
    const int i = blockIdx.x * 256 + threadIdx.x;
    float4 v = ((const float4*)x)[i];
    __half2* dst = (__half2*)g_Xh;
    dst[2 * i]     = __floats2half2_rn(v.x, v.y);
    dst[2 * i + 1] = __floats2half2_rn(v.z, v.w);
}

template <int WHICH>
__global__ void __launch_bounds__(384) prep_wth(const float* __restrict__ w) {
    const int N = WHICH ? 384 : 1152;
    __half* wt = WHICH ? g_W2h : g_W1h;
    const int n = blockIdx.x;
    const int k = threadIdx.x;
    wt[n * 384 + k] = __float2half_rn(w[k * N + n]);
}

__global__ void __launch_bounds__(256) prep_bm(const float* __restrict__ mask,
                                               const float* __restrict__ bt,
                                               const int* __restrict__ ri) {
    const int w = blockIdx.x, h = blockIdx.y;
    float* dst = g_BM + (w * HEADS + h) * (NTOK * NTOK);
    const float* mw = mask + w * (NTOK * NTOK);
    for (int i = threadIdx.x; i < NTOK * NTOK; i += 256)
        dst[i] = bt[ri[i] * HEADS + h] + mw[i];
}

// ---------------------------------------------------------------------------
// fp16 mma.sync GEMM, cp.async 3-stage pipeline, ldmatrix fragment feeds.
// (unchanged from R6 — passing, validated)
// ---------------------------------------------------------------------------
#define STG_B  24576
#define NSTG   3
#define DYNSZ  (NSTG * STG_B)

template <int EPI>
__global__ void __launch_bounds__(512) gemm_h(const float* __restrict__ bias,
                                              float* __restrict__ out) {
    extern __shared__ char smem[];
    const uint32_t smem0 = s2u(smem);

    const __half* A  = (EPI == 0) ? g_Xh : g_AOh;
    const __half* Bw = (EPI == 0) ? (const __half*)g_W1h : (const __half*)g_W2h;

    const int tid  = threadIdx.x;
    const int lane = tid & 31;
    const int warp = tid >> 5;
    const int wm   = warp >> 2;
    const int wn   = warp & 3;
    const int colBase = blockIdx.x * 128;
    const int rowBase = blockIdx.y * 256;

    const __half* Ag = A + (size_t)rowBase * 384;
    const __half* Bg = Bw + (size_t)colBase * 384;

    const int am0 = tid >> 2,          ac0 = tid & 3;
    const int am1 = (tid + 512) >> 2,  ac1 = (tid + 512) & 3;
    const int bn  = tid >> 2,          bc  = tid & 3;

#define LOADSTG(s, kt)                                                          \
    do {                                                                        \
        const uint32_t sb = smem0 + (s) * STG_B;                                \
        cp16(sb + ac0 * 4096 + am0 * 16, Ag + am0 * 384 + (kt) * 32 + ac0 * 8); \
        cp16(sb + ac1 * 4096 + am1 * 16, Ag + am1 * 384 + (kt) * 32 + ac1 * 8); \
        cp16(sb + 16384 + bc * 2048 + bn * 16,                                  \
             Bg + bn * 384 + (kt) * 32 + bc * 8);                               \
    } while (0)

    float acc[4][4][4];
#pragma unroll
    for (int mi = 0; mi < 4; mi++)
#pragma unroll
        for (int ni = 0; ni < 4; ni++)
#pragma unroll
            for (int k = 0; k < 4; k++) acc[mi][ni][k] = 0.f;

    LOADSTG(0, 0);
    cp_commit();
    LOADSTG(1, 1);
    cp_commit();

    const int r = lane >> 2;
    const int c = lane & 3;
    const int lr = lane & 7, sel = lane >> 3;
    const uint32_t a_lane = (uint32_t)((lr + (sel & 1) * 8) * 16 + (sel >> 1) * 4096);
    const uint32_t b_lane = (uint32_t)(((sel >> 1) * 8 + lr) * 16 + (sel & 1) * 2048);

    for (int kt = 0; kt < 12; kt++) {
        if (kt < 11) cp_wait<1>(); else cp_wait<0>();
        __syncthreads();
        if (kt + 2 < 12) { LOADSTG((kt + 2) % NSTG, kt + 2); cp_commit(); }

        const uint32_t sb = smem0 + (kt % NSTG) * STG_B;
#pragma unroll
        for (int ks = 0; ks < 2; ks++) {
            unsigned af[4][4], bf[4][2];
#pragma unroll
            for (int mi = 0; mi < 4; mi++)
                ldsm4(af[mi], sb + (2 * ks) * 4096 + (wm * 64 + mi * 16) * 16 + a_lane);
#pragma unroll
            for (int p = 0; p < 2; p++) {
                unsigned t[4];
                ldsm4(t, sb + 16384 + (2 * ks) * 2048 + (wn * 32 + p * 16) * 16 + b_lane);
                bf[2 * p][0] = t[0]; bf[2 * p][1] = t[1];
                bf[2 * p + 1][0] = t[2]; bf[2 * p + 1][1] = t[3];
            }
#pragma unroll
            for (int mi = 0; mi < 4; mi++)
#pragma unroll
                for (int ni = 0; ni < 4; ni++) mma16(acc[mi][ni], af[mi], bf[ni]);
        }
        __syncthreads();
    }

#pragma unroll
    for (int mi = 0; mi < 4; mi++) {
#pragma unroll
        for (int g = 0; g < 2; g++) {
            const int row = rowBase + wm * 64 + mi * 16 + r + g * 8;
            int bb = 0, n = 0;
            if (EPI == 0) { bb = row / 49; n = row - bb * 49; }
#pragma unroll
            for (int ni = 0; ni < 4; ni++) {
                const int col = colBase + wn * 32 + ni * 8 + 2 * c;
                float2 b2 = *(const float2*)(bias + col);
                float2 v;
                v.x = acc[mi][ni][g * 2 + 0] + b2.x;
                v.y = acc[mi][ni][g * 2 + 1] + b2.y;
                if (EPI == 0) {
                    const int which = (col >= 768) ? 2 : (col >= 384 ? 1 : 0);
                    const int ccc = col - which * 384;
                    const int h = ccc >> 5, dd = ccc & 31;
                    const size_t di = ((size_t)(bb * 12 + h) * 49 + n) * 32 + dd;
                    if (which == 0) {
                        v.x *= 0.17677669529663689f;
                        v.y *= 0.17677669529663689f;
                        *(__half2*)(g_Qh + di) = __floats2half2_rn(v.x, v.y);
                    } else if (which == 1) {
                        *(__half2*)(g_Kh + di) = __floats2half2_rn(v.x, v.y);
                    } else {
                        *(__half2*)(g_Vh + di) = __floats2half2_rn(v.x, v.y);
                    }
                } else {
                    *(float2*)(out + (size_t)row * 384 + col) = v;
                }
            }
        }
    }
#undef LOADSTG
}

// ---------------------------------------------------------------------------
// Register-resident tensor-core attention.
// One CTA (128 threads = 4 warps) per (window b, head h).
// Warp owns a 16-ROW strip: S rows stay in registers through softmax and PV.
// ---------------------------------------------------------------------------
#define AQ_STR 40   // halfs per row (80B; ldmatrix row banks 20r: all distinct)

__global__ void __launch_bounds__(128) attn_mma() {
    __shared__ __half sQ[64 * AQ_STR];
    __shared__ __half sK[64 * AQ_STR];
    __shared__ __half sV[64 * AQ_STR];

    const int b = blockIdx.x;
    const int h = blockIdx.y;
    const int tid = threadIdx.x;
    const int lane = tid & 31;
    const int warp = tid >> 5;

    const __half* Qb = g_Qh + (size_t)(b * 12 + h) * 1568;
    const __half* Kb = g_Kh + (size_t)(b * 12 + h) * 1568;
    const __half* Vb = g_Vh + (size_t)(b * 12 + h) * 1568;

    // zero V pad rows 49..63 (0 x NaN hazard into valid output rows)
    {
        uint4 z = {0u, 0u, 0u, 0u};
        uint4* vp = (uint4*)(sV + 49 * AQ_STR);   // 15*40 halfs = 75 uint4
        for (int i = tid; i < 75; i += 128) vp[i] = z;
    }

    // load Q,K,V row-major (vectorized)
    for (int f = tid; f < 196; f += 128) {
        const int row = f >> 2, ch = (f & 3) * 8;
        *(uint4*)&sQ[row * AQ_STR + ch] = *(const uint4*)(Qb + row * 32 + ch);
        *(uint4*)&sK[row * AQ_STR + ch] = *(const uint4*)(Kb + row * 32 + ch);
        *(uint4*)&sV[row * AQ_STR + ch] = *(const uint4*)(Vb + row * 32 + ch);
    }
    __syncthreads();

    const int r = lane >> 2, c = lane & 3;
    const int lr = lane & 7, sel = lane >> 3;
    const float* bm = g_BM + ((size_t)(b & 63) * 12 + h) * 2401;

    const uint32_t sQb = s2u(sQ), sKb = s2u(sK), sVb = s2u(sV);
    const uint32_t qp_lane80 = (uint32_t)((lr + (sel & 1) * 8) * 80 + (sel >> 1) * 16);
    const uint32_t k_lane80  = (uint32_t)((((sel >> 1) * 8) + lr) * 80 + (sel & 1) * 16);
    const uint32_t v_lane80  = (uint32_t)((lr + ((lane >> 3) & 1) * 8) * 80);

    // ---- Phase 1: S[m-strip][0..63] = Q Kt, all in registers.
    const int m0 = warp * 16;
    unsigned aQ[2][4];
#pragma unroll
    for (int ks = 0; ks < 2; ks++)
        ldsm4(aQ[ks], sQb + m0 * 80 + ks * 32 + qp_lane80);

    unsigned bK[2][4][4];   // [ks][n-strip16][t]
#pragma unroll
    for (int ks = 0; ks < 2; ks++)
#pragma unroll
        for (int st = 0; st < 4; st++)
            ldsm4(bK[ks][st], sKb + st * 16 * 80 + ks * 32 + k_lane80);

    float acc[8][4];
#pragma unroll
    for (int nt = 0; nt < 8; nt++)
#pragma unroll
        for (int j = 0; j < 4; j++) acc[nt][j] = 0.f;

#pragma unroll
    for (int ks = 0; ks < 2; ks++)
#pragma unroll
        for (int st = 0; st < 4; st++) {
            mma16(acc[st * 2 + 0], aQ[ks], &bK[ks][st][0]);
            mma16(acc[st * 2 + 1], aQ[ks], &bK[ks][st][2]);
        }

    // ---- Phase 2: bias+mask + softmax, register-resident.
    const int row0 = m0 + r;
    const int row1 = row0 + 8;
    const int rc0 = (row0 < 49 ? row0 : 48) * 49;
    const int rc1 = (row1 < 49 ? row1 : 48) * 49;

    float mx0 = -3.0e38f, mx1 = -3.0e38f;
#pragma unroll
    for (int nt = 0; nt < 8; nt++) {
        const int col = nt * 8 + 2 * c;
        acc[nt][0] = (col < 49)     ? acc[nt][0] + bm[rc0 + col]     : -1e30f;
        acc[nt][1] = (col + 1 < 49) ? acc[nt][1] + bm[rc0 + col + 1] : -1e30f;
        acc[nt][2] = (col < 49)     ? acc[nt][2] + bm[rc1 + col]     : -1e30f;
        acc[nt][3] = (col + 1 < 49) ? acc[nt][3] + bm[rc1 + col + 1] : -1e30f;
        mx0 = fmaxf(mx0, fmaxf(acc[nt][0], acc[nt][1]));
        mx1 = fmaxf(mx1, fmaxf(acc[nt][2], acc[nt][3]));
    }
    mx0 = fmaxf(mx0, __shfl_xor_sync(0xffffffffu, mx0, 1));
    mx0 = fmaxf(mx0, __shfl_xor_sync(0xffffffffu, mx0, 2));
    mx1 = fmaxf(mx1, __shfl_xor_sync(0xffffffffu, mx1, 1));
    mx1 = fmaxf(mx1, __shfl_xor_sync(0xffffffffu, mx1, 2));

    float sm0 = 0.f, sm1 = 0.f;
#pragma unroll
    for (int nt = 0; nt < 8; nt++) {
        acc[nt][0] = __expf(acc[nt][0] - mx0);
        acc[nt][1] = __expf(acc[nt][1] - mx0);
        acc[nt][2] = __expf(acc[nt][2] - mx1);
        acc[nt][3] = __expf(acc[nt][3] - mx1);
        sm0 += acc[nt][0] + acc[nt][1];
        sm1 += acc[nt][2] + acc[nt][3];
    }
    sm0 += __shfl_xor_sync(0xffffffffu, sm0, 1);
    sm0 += __shfl_xor_sync(0xffffffffu, sm0, 2);
    sm1 += __shfl_xor_sync(0xffffffffu, sm1, 1);
    sm1 += __shfl_xor_sync(0xffffffffu, sm1, 2);
    const float inv0 = 1.f / sm0;
    const float inv1 = 1.f / sm1;

    // pack P: C-fragment layout == A-fragment layout
    unsigned pA[8], pB[8];
#pragma unroll
    for (int nt = 0; nt < 8; nt++) {
        pA[nt] = pack_h2(acc[nt][0] * inv0, acc[nt][1] * inv0);
        pB[nt] = pack_h2(acc[nt][2] * inv1, acc[nt][3] * inv1);
    }

    // ---- Phase 3: O = P V, V fragments via ldmatrix.trans.
    unsigned bV[4][4][2];   // [ks][d-strip8][b0,b1]
#pragma unroll
    for (int j = 0; j < 4; j++)
#pragma unroll
        for (int nt = 0; nt < 4; nt++)
            ldsm2t(bV[j][nt], sVb + j * 16 * 80 + v_lane80 + nt * 16);

    float oacc[4][4];
#pragma unroll
    for (int nt = 0; nt < 4; nt++)
#pragma unroll
        for (int j = 0; j < 4; j++) oacc[nt][j] = 0.f;

#pragma unroll
    for (int j = 0; j < 4; j++) {
        unsigned a[4] = {pA[2 * j], pB[2 * j], pA[2 * j + 1], pB[2 * j + 1]};
#pragma unroll
        for (int nt = 0; nt < 4; nt++) mma16(oacc[nt], a, bV[j][nt]);
    }

    __half* AOb = g_AOh + (size_t)b * 49 * 384 + h * 32;
#pragma unroll
    for (int nt = 0; nt < 4; nt++) {
        const int col = nt * 8 + 2 * c;
        if (row0 < 49)
            *(__half2*)&AOb[row0 * 384 + col] = __floats2half2_rn(oacc[nt][0], oacc[nt][1]);
        if (row1 < 49)
            *(__half2*)&AOb[row1 * 384 + col] = __floats2half2_rn(oacc[nt][2], oacc[nt][3]);
    }
}

// ---------------------------------------------------------------------------
extern "C" void kernel_launch(void* const* d_in, const int* in_sizes, int n_in,
                              void* d_out, int out_size) {
    const float* x          = (const float*)d_in[0];
    const float* mask       = (const float*)d_in[1];
    const float* qkv_w      = (const float*)d_in[2];
    const float* qkv_b      = (const float*)d_in[3];
    const float* proj_w     = (const float*)d_in[4];
    const float* proj_b     = (const float*)d_in[5];
    const float* bias_table = (const float*)d_in[6];
    const int*   rel_idx    = (const int*)d_in[7];
    float*       out        = (float*)d_out;

    cudaFuncSetAttribute(gemm_h<0>, cudaFuncAttributeMaxDynamicSharedMemorySize, DYNSZ);
    cudaFuncSetAttribute(gemm_h<1>, cudaFuncAttributeMaxDynamicSharedMemorySize, DYNSZ);

    prep_xh<<<37632, 256>>>(x);
    prep_wth<0><<<1152, 384>>>(qkv_w);
    prep_wth<1><<<384, 384>>>(proj_w);
    prep_bm<<<dim3(NWIN, HEADS), 256>>>(mask, bias_table, rel_idx);

    gemm_h<0><<<dim3(9, 392), 512, DYNSZ>>>(qkv_b, nullptr);

    attn_mma<<<dim3(2048, 12), 128>>>();

    gemm_h<1><<<dim3(3, 392), 512, DYNSZ>>>(proj_b, out);
}